// round 2
// baseline (speedup 1.0000x reference)
#include <cuda_runtime.h>

// ---------------------------------------------------------------------------
// Transformer-XL relative multi-head attention, fp32.
// B=16, T=512, D=512, H=8, hd=64, P=2T-1=1023.
//
// rel_shift identity: shifted[b,h,t,j] = pos_score[b,h,t, (T-1)+j-t]
// so we scatter-add the pos GEMM output directly into the score matrix.
// ---------------------------------------------------------------------------

#define NB 16
#define NT 512
#define ND 512
#define NH 8
#define HD 64
#define NP (2*NT - 1)   // 1023

// Scratch (device globals; allocation-free per harness rules)
__device__ float g_xn [NB*NT*ND];
__device__ float g_q  [NB*NT*ND];
__device__ float g_kk [NB*NT*ND];
__device__ float g_v  [NB*NT*ND];
__device__ float g_pp [NB*NP*ND];
__device__ float g_S  [(size_t)NB*NH*NT*NT];   // 134 MB
__device__ float g_ctx[NB*NT*ND];

// ---------------------------------------------------------------------------
// LayerNorm: one block (256 thr) per row of 512
// ---------------------------------------------------------------------------
__global__ void ln_kernel(const float* __restrict__ x,
                          const float* __restrict__ gam,
                          const float* __restrict__ bet,
                          float* __restrict__ xn) {
    int row = blockIdx.x;
    int tid = threadIdx.x;
    const float* xr = x + (size_t)row * ND;
    float v0 = xr[tid], v1 = xr[tid + 256];
    float s = v0 + v1, ss = v0*v0 + v1*v1;
    #pragma unroll
    for (int o = 16; o > 0; o >>= 1) {
        s  += __shfl_down_sync(0xffffffffu, s,  o);
        ss += __shfl_down_sync(0xffffffffu, ss, o);
    }
    __shared__ float sh[16];
    __shared__ float smu, srs;
    int wid = tid >> 5, lane = tid & 31;
    if (lane == 0) { sh[wid] = s; sh[wid + 8] = ss; }
    __syncthreads();
    if (tid == 0) {
        float t1 = 0.f, t2 = 0.f;
        #pragma unroll
        for (int i = 0; i < 8; i++) { t1 += sh[i]; t2 += sh[i + 8]; }
        float mu  = t1 * (1.0f / ND);
        float var = t2 * (1.0f / ND) - mu * mu;
        smu = mu;
        srs = rsqrtf(var + 1e-5f);
    }
    __syncthreads();
    float mu = smu, rs = srs;
    float* xo = xn + (size_t)row * ND;
    xo[tid]       = (v0 - mu) * rs * gam[tid]       + bet[tid];
    xo[tid + 256] = (v1 - mu) * rs * gam[tid + 256] + bet[tid + 256];
}

// ---------------------------------------------------------------------------
// C[M,512] = A[M,512] @ W[512,512]^T + bias   (both operands K-contiguous)
// 64x64 tile, BK=16, 256 threads, 4x4 per thread
// ---------------------------------------------------------------------------
__global__ void gemm_nt(const float* __restrict__ A, const float* __restrict__ W,
                        const float* __restrict__ bias, float* __restrict__ C,
                        int M) {
    __shared__ float As[64][17];
    __shared__ float Bs[64][17];
    int tid = threadIdx.x;
    int n0 = blockIdx.x * 64, m0 = blockIdx.y * 64;
    int lr = tid >> 2;             // 0..63 tile row
    int lk = (tid & 3) * 4;        // 0,4,8,12
    int tx = tid & 15, ty = tid >> 4;
    float acc[4][4];
    #pragma unroll
    for (int i = 0; i < 4; i++)
        #pragma unroll
        for (int j = 0; j < 4; j++) acc[i][j] = 0.f;

    for (int ks = 0; ks < 512; ks += 16) {
        float4 av = make_float4(0.f, 0.f, 0.f, 0.f);
        int arow = m0 + lr;
        if (arow < M)
            av = *reinterpret_cast<const float4*>(A + (size_t)arow * 512 + ks + lk);
        float4 bv = *reinterpret_cast<const float4*>(W + (size_t)(n0 + lr) * 512 + ks + lk);
        __syncthreads();
        As[lr][lk + 0] = av.x; As[lr][lk + 1] = av.y;
        As[lr][lk + 2] = av.z; As[lr][lk + 3] = av.w;
        Bs[lr][lk + 0] = bv.x; Bs[lr][lk + 1] = bv.y;
        Bs[lr][lk + 2] = bv.z; Bs[lr][lk + 3] = bv.w;
        __syncthreads();
        #pragma unroll
        for (int k = 0; k < 16; k++) {
            float a[4], b[4];
            #pragma unroll
            for (int i = 0; i < 4; i++) { a[i] = As[ty*4 + i][k]; b[i] = Bs[tx*4 + i][k]; }
            #pragma unroll
            for (int i = 0; i < 4; i++)
                #pragma unroll
                for (int j = 0; j < 4; j++) acc[i][j] += a[i] * b[j];
        }
    }
    #pragma unroll
    for (int i = 0; i < 4; i++) {
        int row = m0 + ty*4 + i;
        if (row < M) {
            #pragma unroll
            for (int j = 0; j < 4; j++) {
                int col = n0 + tx*4 + j;
                C[(size_t)row * 512 + col] = acc[i][j] + __ldg(&bias[col]);
            }
        }
    }
}

// ---------------------------------------------------------------------------
// Attention score GEMMs, K=64 single shot.
// REL=false: S[s, t]  = (q[s]+cb) . k[t]          (writes)
// REL=true : S[s, p-511+s] += (q[s]+pb) . p_emb[p] (scatter-add, rel_shift)
// grid: (N/64, T/64, B*H), 256 threads, 64x64 tile, 4x4 per thread
// ---------------------------------------------------------------------------
template <bool REL>
__global__ void attn_gemm(const float* __restrict__ Q, const float* __restrict__ KP,
                          const float* __restrict__ abias, float* __restrict__ S,
                          int rowsB) {
    int z  = blockIdx.z; int b = z >> 3, h = z & 7;
    int t0 = blockIdx.y * 64, n0 = blockIdx.x * 64;
    if (REL) {
        // valid iff exists p+t in [511, 1022]
        int lo = n0 + t0, hi = n0 + t0 + 126;
        if (hi < NT - 1 || lo > 2*NT - 2) return;
    }
    const float* Aq = Q  + (size_t)b * NT    * ND + h * HD;
    const float* Bk = KP + (size_t)b * rowsB * ND + h * HD;

    __shared__ float As[64][65];
    __shared__ float Bs[64][65];
    __shared__ float bsh[64];

    int tid = threadIdx.x;
    if (tid < 64) bsh[tid] = abias[h * HD + tid];
    __syncthreads();

    int lr = tid >> 2;            // tile row 0..63
    int lk = (tid & 3) * 16;      // 0,16,32,48
    {
        const float4* asrc = reinterpret_cast<const float4*>(Aq + (size_t)(t0 + lr) * ND + lk);
        #pragma unroll
        for (int i = 0; i < 4; i++) {
            float4 v = asrc[i];
            int k = lk + i * 4;
            As[lr][k + 0] = v.x + bsh[k + 0];
            As[lr][k + 1] = v.y + bsh[k + 1];
            As[lr][k + 2] = v.z + bsh[k + 2];
            As[lr][k + 3] = v.w + bsh[k + 3];
        }
        int brow = n0 + lr;
        if (brow < rowsB) {
            const float4* bsrc = reinterpret_cast<const float4*>(Bk + (size_t)brow * ND + lk);
            #pragma unroll
            for (int i = 0; i < 4; i++) {
                float4 v = bsrc[i];
                int k = lk + i * 4;
                Bs[lr][k + 0] = v.x; Bs[lr][k + 1] = v.y;
                Bs[lr][k + 2] = v.z; Bs[lr][k + 3] = v.w;
            }
        } else {
            #pragma unroll
            for (int i = 0; i < 16; i++) Bs[lr][lk + i] = 0.f;
        }
    }
    __syncthreads();

    int tx = tid & 15, ty = tid >> 4;
    float acc[4][4];
    #pragma unroll
    for (int i = 0; i < 4; i++)
        #pragma unroll
        for (int j = 0; j < 4; j++) acc[i][j] = 0.f;

    #pragma unroll 16
    for (int k = 0; k < 64; k++) {
        float a[4], bb[4];
        #pragma unroll
        for (int i = 0; i < 4; i++) { a[i] = As[ty*4 + i][k]; bb[i] = Bs[tx*4 + i][k]; }
        #pragma unroll
        for (int i = 0; i < 4; i++)
            #pragma unroll
            for (int j = 0; j < 4; j++) acc[i][j] += a[i] * bb[j];
    }

    float* Sz = S + (size_t)z * NT * NT;
    if (!REL) {
        #pragma unroll
        for (int i = 0; i < 4; i++)
            #pragma unroll
            for (int j = 0; j < 4; j++)
                Sz[(size_t)(t0 + ty*4 + i) * NT + (n0 + tx*4 + j)] = acc[i][j];
    } else {
        #pragma unroll
        for (int i = 0; i < 4; i++) {
            int t = t0 + ty*4 + i;
            #pragma unroll
            for (int j = 0; j < 4; j++) {
                int p  = n0 + tx*4 + j;
                int jj = p - (NT - 1) + t;
                if (p < rowsB && jj >= 0 && jj < NT)
                    Sz[(size_t)t * NT + jj] += acc[i][j];
            }
        }
    }
}

// ---------------------------------------------------------------------------
// Softmax over rows of 512, scale 1/sqrt(64)=0.125 folded in. In place.
// ---------------------------------------------------------------------------
__global__ void softmax_kernel(float* __restrict__ S) {
    size_t row = blockIdx.x;
    float* r = S + row * NT;
    int tid = threadIdx.x;
    float v0 = r[tid] * 0.125f, v1 = r[tid + 256] * 0.125f;
    float m = fmaxf(v0, v1);
    #pragma unroll
    for (int o = 16; o > 0; o >>= 1) m = fmaxf(m, __shfl_xor_sync(0xffffffffu, m, o));
    __shared__ float shm[8];
    __shared__ float shs[8];
    int wid = tid >> 5, lane = tid & 31;
    if (lane == 0) shm[wid] = m;
    __syncthreads();
    float M = shm[0];
    #pragma unroll
    for (int i = 1; i < 8; i++) M = fmaxf(M, shm[i]);
    float e0 = __expf(v0 - M), e1 = __expf(v1 - M);
    float s = e0 + e1;
    #pragma unroll
    for (int o = 16; o > 0; o >>= 1) s += __shfl_xor_sync(0xffffffffu, s, o);
    if (lane == 0) shs[wid] = s;
    __syncthreads();
    float tot = 0.f;
    #pragma unroll
    for (int i = 0; i < 8; i++) tot += shs[i];
    float inv = 1.0f / tot;
    r[tid]       = e0 * inv;
    r[tid + 256] = e1 * inv;
}

// ---------------------------------------------------------------------------
// ctx[b,s,h,:] = sum_t W[s,t] * v[b,t,h,:]  per (b,h): [512,512]x[512,64]
// grid: (T/64, B*H)
// ---------------------------------------------------------------------------
__global__ void ctx_gemm(const float* __restrict__ S, const float* __restrict__ V,
                         float* __restrict__ ctx) {
    int z = blockIdx.y; int b = z >> 3, h = z & 7;
    int m0 = blockIdx.x * 64;
    const float* A  = S + (size_t)z * NT * NT;
    const float* Bv = V + (size_t)b * NT * ND + h * HD;

    __shared__ float As[64][17];
    __shared__ float Bs[16][65];
    int tid = threadIdx.x;
    int alr = tid >> 2, alk = (tid & 3) * 4;
    int blr = tid >> 4, bln = (tid & 15) * 4;
    int tx = tid & 15, ty = tid >> 4;
    float acc[4][4];
    #pragma unroll
    for (int i = 0; i < 4; i++)
        #pragma unroll
        for (int j = 0; j < 4; j++) acc[i][j] = 0.f;

    for (int ks = 0; ks < 512; ks += 16) {
        float4 av = *reinterpret_cast<const float4*>(A  + (size_t)(m0 + alr) * NT + ks + alk);
        float4 bv = *reinterpret_cast<const float4*>(Bv + (size_t)(ks + blr) * ND + bln);
        __syncthreads();
        As[alr][alk + 0] = av.x; As[alr][alk + 1] = av.y;
        As[alr][alk + 2] = av.z; As[alr][alk + 3] = av.w;
        Bs[blr][bln + 0] = bv.x; Bs[blr][bln + 1] = bv.y;
        Bs[blr][bln + 2] = bv.z; Bs[blr][bln + 3] = bv.w;
        __syncthreads();
        #pragma unroll
        for (int k = 0; k < 16; k++) {
            float a[4], bb[4];
            #pragma unroll
            for (int i = 0; i < 4; i++) { a[i] = As[ty*4 + i][k]; bb[i] = Bs[k][tx*4 + i]; }
            #pragma unroll
            for (int i = 0; i < 4; i++)
                #pragma unroll
                for (int j = 0; j < 4; j++) acc[i][j] += a[i] * bb[j];
        }
    }
    #pragma unroll
    for (int i = 0; i < 4; i++) {
        int srow = m0 + ty*4 + i;
        #pragma unroll
        for (int j = 0; j < 4; j++)
            ctx[(size_t)(b * NT + srow) * ND + h * HD + tx*4 + j] = acc[i][j];
    }
}

// ---------------------------------------------------------------------------
extern "C" void kernel_launch(void* const* d_in, const int* in_sizes, int n_in,
                              void* d_out, int out_size) {
    const float* x    = (const float*)d_in[0];
    const float* pos  = (const float*)d_in[1];
    const float* ln_g = (const float*)d_in[2];
    const float* ln_b = (const float*)d_in[3];
    const float* Wq   = (const float*)d_in[4];
    const float* bq   = (const float*)d_in[5];
    const float* Wk   = (const float*)d_in[6];
    const float* bk   = (const float*)d_in[7];
    const float* Wv   = (const float*)d_in[8];
    const float* bv   = (const float*)d_in[9];
    const float* Wp   = (const float*)d_in[10];
    const float* bp   = (const float*)d_in[11];
    const float* cb   = (const float*)d_in[12];
    const float* pb   = (const float*)d_in[13];
    const float* Wo   = (const float*)d_in[14];
    const float* bo   = (const float*)d_in[15];
    float* out = (float*)d_out;

    float *xn, *q, *k, *v, *p, *S, *ctx;
    cudaGetSymbolAddress((void**)&xn,  g_xn);
    cudaGetSymbolAddress((void**)&q,   g_q);
    cudaGetSymbolAddress((void**)&k,   g_kk);
    cudaGetSymbolAddress((void**)&v,   g_v);
    cudaGetSymbolAddress((void**)&p,   g_pp);
    cudaGetSymbolAddress((void**)&S,   g_S);
    cudaGetSymbolAddress((void**)&ctx, g_ctx);

    // 1. LayerNorm
    ln_kernel<<<NB * NT, 256>>>(x, ln_g, ln_b, xn);

    // 2. Q/K/V projections  [8192,512] x [512,512]^T
    dim3 g1(8, (NB * NT) / 64);
    gemm_nt<<<g1, 256>>>(xn, Wq, bq, q, NB * NT);
    gemm_nt<<<g1, 256>>>(xn, Wk, bk, k, NB * NT);
    gemm_nt<<<g1, 256>>>(xn, Wv, bv, v, NB * NT);

    // 3. P projection  [16368,512] x [512,512]^T
    dim3 gp(8, (NB * NP + 63) / 64);
    gemm_nt<<<gp, 256>>>(pos, Wp, bp, p, NB * NP);

    // 4. Content scores: S[s,t] = (q+cb).k
    dim3 gc(NT / 64, NT / 64, NB * NH);
    attn_gemm<false><<<gc, 256>>>(q, k, cb, S, NT);

    // 5. Pos scores with fused rel_shift scatter-add
    dim3 gr((NP + 63) / 64, NT / 64, NB * NH);
    attn_gemm<true><<<gr, 256>>>(q, p, pb, S, NP);

    // 6. Softmax (scale folded)
    softmax_kernel<<<NB * NH * NT, 256>>>(S);

    // 7. ctx = W @ V
    dim3 gx(NT / 64, NB * NH);
    ctx_gemm<<<gx, 256>>>(S, v, ctx);

    // 8. Output projection -> d_out
    gemm_nt<<<g1, 256>>>(ctx, Wo, bo, out, NB * NT);
}

// round 5
// speedup vs baseline: 1.8105x; 1.8105x over previous
#include <cuda_runtime.h>

// ---------------------------------------------------------------------------
// Transformer-XL relative multi-head attention, TF32 tensor-core version.
// B=16, T=512, D=512, H=8, hd=64, P=2T-1=1023.
// rel_shift identity: shifted[b,h,t,j] = pos_score[b,h,t, (T-1)+j-t]
// ---------------------------------------------------------------------------

#define NB 16
#define NT 512
#define ND 512
#define NH 8
#define HD 64
#define NP (2*NT - 1)   // 1023

__device__ float g_xn [NB*NT*ND];
__device__ float g_q  [NB*NT*ND];
__device__ float g_kk [NB*NT*ND];
__device__ float g_v  [NB*NT*ND];
__device__ float g_pp [NB*NP*ND];
__device__ float g_S  [(size_t)NB*NH*NT*NT];   // 134 MB
__device__ float g_ctx[NB*NT*ND];

// ---------------------------------------------------------------------------
// TF32 helpers
// ---------------------------------------------------------------------------
__device__ __forceinline__ unsigned f2tf32(float x) {
    unsigned u;
    asm("cvt.rna.tf32.f32 %0, %1;" : "=r"(u) : "f"(x));
    return u;
}

__device__ __forceinline__ void mma_tf32(float* d, const unsigned* a, const unsigned* b) {
    asm volatile(
        "mma.sync.aligned.m16n8k8.row.col.f32.tf32.tf32.f32 "
        "{%0,%1,%2,%3}, {%4,%5,%6,%7}, {%8,%9}, {%0,%1,%2,%3};"
        : "+f"(d[0]), "+f"(d[1]), "+f"(d[2]), "+f"(d[3])
        : "r"(a[0]), "r"(a[1]), "r"(a[2]), "r"(a[3]), "r"(b[0]), "r"(b[1]));
}

// ---------------------------------------------------------------------------
// LayerNorm: one block (256 thr) per row of 512
// ---------------------------------------------------------------------------
__global__ void ln_kernel(const float* __restrict__ x,
                          const float* __restrict__ gam,
                          const float* __restrict__ bet,
                          float* __restrict__ xn) {
    int row = blockIdx.x;
    int tid = threadIdx.x;
    const float* xr = x + (size_t)row * ND;
    float v0 = xr[tid], v1 = xr[tid + 256];
    float s = v0 + v1, ss = v0*v0 + v1*v1;
    #pragma unroll
    for (int o = 16; o > 0; o >>= 1) {
        s  += __shfl_down_sync(0xffffffffu, s,  o);
        ss += __shfl_down_sync(0xffffffffu, ss, o);
    }
    __shared__ float sh[16];
    __shared__ float smu, srs;
    int wid = tid >> 5, lane = tid & 31;
    if (lane == 0) { sh[wid] = s; sh[wid + 8] = ss; }
    __syncthreads();
    if (tid == 0) {
        float t1 = 0.f, t2 = 0.f;
        #pragma unroll
        for (int i = 0; i < 8; i++) { t1 += sh[i]; t2 += sh[i + 8]; }
        float mu  = t1 * (1.0f / ND);
        float var = t2 * (1.0f / ND) - mu * mu;
        smu = mu;
        srs = rsqrtf(var + 1e-5f);
    }
    __syncthreads();
    float mu = smu, rs = srs;
    float* xo = xn + (size_t)row * ND;
    xo[tid]       = (v0 - mu) * rs * gam[tid]       + bet[tid];
    xo[tid + 256] = (v1 - mu) * rs * gam[tid + 256] + bet[tid + 256];
}

// ---------------------------------------------------------------------------
// TF32 projection GEMM: C[M,512] = A[M,512] @ W[512,512]^T + bias
// Block tile 128x128, BK=16, 256 threads = 8 warps (2x4), warp tile 64x32.
// Smem swizzle (16-col rows): scol = col ^ (4*((row>>1)&3)) -> frag loads
// conflict-free (bank = (row&1)<<4 | scol is bijective over the warp).
// ---------------------------------------------------------------------------
__global__ __launch_bounds__(256) void gemm_nt_tc(const float* __restrict__ A,
                                                  const float* __restrict__ W,
                                                  const float* __restrict__ bias,
                                                  float* __restrict__ C, int M) {
    __shared__ unsigned As[2][128 * 16];
    __shared__ unsigned Bs[2][128 * 16];
    const int tid = threadIdx.x, lane = tid & 31, wid = tid >> 5;
    const int g = lane >> 2, cq = lane & 3;
    const int wm = (wid >> 2) * 64, wn = (wid & 3) * 32;
    const int m0 = blockIdx.y * 128, n0 = blockIdx.x * 128;
    const int sza = 4 * ((g >> 1) & 3);   // uniform frag-row swizzle (row>>1)&3 == (g>>1)&3

    float acc[16][4];
    #pragma unroll
    for (int i = 0; i < 16; i++)
        #pragma unroll
        for (int j = 0; j < 4; j++) acc[i][j] = 0.f;

    float4 ra[2], rb[2];

    // global fetch of one BK-chunk into registers
    auto gload = [&](int kc) {
        #pragma unroll
        for (int i = 0; i < 2; i++) {
            int idx = tid + i * 256;           // 512 float4s per tile
            int r = idx >> 2, cc = (idx & 3) * 4;
            int arow = m0 + r;
            if (arow < M)
                ra[i] = *reinterpret_cast<const float4*>(A + (size_t)arow * 512 + kc * 16 + cc);
            else
                ra[i] = make_float4(0.f, 0.f, 0.f, 0.f);
            rb[i] = *reinterpret_cast<const float4*>(W + (size_t)(n0 + r) * 512 + kc * 16 + cc);
        }
    };
    auto sstore = [&](int buf) {
        #pragma unroll
        for (int i = 0; i < 2; i++) {
            int idx = tid + i * 256;
            int r = idx >> 2, cc = (idx & 3) * 4;
            int sc = cc ^ (4 * ((r >> 1) & 3));
            unsigned* pa = &As[buf][r * 16 + sc];
            pa[0] = f2tf32(ra[i].x); pa[1] = f2tf32(ra[i].y);
            pa[2] = f2tf32(ra[i].z); pa[3] = f2tf32(ra[i].w);
            unsigned* pb = &Bs[buf][r * 16 + sc];
            pb[0] = f2tf32(rb[i].x); pb[1] = f2tf32(rb[i].y);
            pb[2] = f2tf32(rb[i].z); pb[3] = f2tf32(rb[i].w);
        }
    };
    auto compute = [&](int buf) {
        #pragma unroll
        for (int ks = 0; ks < 2; ks++) {
            int colb = ks * 8 + cq;
            unsigned af[4][4], bf[4][2];
            #pragma unroll
            for (int i = 0; i < 4; i++) {
                int r = wm + i * 16 + g;
                af[i][0] = As[buf][r * 16 + (colb ^ sza)];
                af[i][1] = As[buf][(r + 8) * 16 + (colb ^ sza)];
                af[i][2] = As[buf][r * 16 + ((colb + 4) ^ sza)];
                af[i][3] = As[buf][(r + 8) * 16 + ((colb + 4) ^ sza)];
            }
            #pragma unroll
            for (int j = 0; j < 4; j++) {
                int r = wn + j * 8 + g;
                bf[j][0] = Bs[buf][r * 16 + (colb ^ sza)];
                bf[j][1] = Bs[buf][r * 16 + ((colb + 4) ^ sza)];
            }
            #pragma unroll
            for (int i = 0; i < 4; i++)
                #pragma unroll
                for (int j = 0; j < 4; j++)
                    mma_tf32(acc[i * 4 + j], af[i], bf[j]);
        }
    };

    gload(0);
    sstore(0);
    __syncthreads();
    for (int kc = 0; kc < 32; kc++) {
        if (kc < 31) gload(kc + 1);
        compute(kc & 1);
        if (kc < 31) sstore((kc + 1) & 1);
        __syncthreads();
    }

    #pragma unroll
    for (int i = 0; i < 4; i++) {
        int row = m0 + wm + i * 16 + g;
        #pragma unroll
        for (int j = 0; j < 4; j++) {
            int col = n0 + wn + j * 8 + 2 * cq;
            float b0 = __ldg(&bias[col]), b1 = __ldg(&bias[col + 1]);
            float* v = acc[i * 4 + j];
            if (row < M) {
                C[(size_t)row * 512 + col]     = v[0] + b0;
                C[(size_t)row * 512 + col + 1] = v[1] + b1;
            }
            if (row + 8 < M) {
                C[(size_t)(row + 8) * 512 + col]     = v[2] + b0;
                C[(size_t)(row + 8) * 512 + col + 1] = v[3] + b1;
            }
        }
    }
}

// ---------------------------------------------------------------------------
// TF32 attention score GEMMs, K=64 single shot.
// REL=false: S[s,t]  = (q[s]+cb).k[t]            (writes)
// REL=true : S[s,p-511+s] += (q[s]+pb).p_emb[p]  (rel_shift scatter-add)
// Block 64x64, 128 threads = 4 warps (2x2), warp tile 32x32.
// Smem swizzle (64-col rows): scol = col ^ (4*(row&7)), row&7 == g for frags.
// ---------------------------------------------------------------------------
template <bool REL>
__global__ __launch_bounds__(128) void attn_score_tc(const float* __restrict__ Q,
                                                     const float* __restrict__ KP,
                                                     const float* __restrict__ abias,
                                                     float* __restrict__ S, int rowsB) {
    int z = blockIdx.z, b = z >> 3, h = z & 7;
    int t0 = blockIdx.y * 64, n0 = blockIdx.x * 64;
    if (REL) {
        int lo = n0 + t0, hi = n0 + t0 + 126;
        if (hi < NT - 1 || lo > 2 * NT - 2) return;
    }
    __shared__ unsigned Qs[64 * 64];
    __shared__ unsigned Ks[64 * 64];
    int tid = threadIdx.x, lane = tid & 31, wid = tid >> 5;
    int g = lane >> 2, cq = lane & 3;
    int wm = (wid >> 1) * 32, wn = (wid & 1) * 32;
    const int sz = 4 * g;

    const float* qb = Q  + (size_t)b * NT    * ND + h * HD;
    const float* kb = KP + (size_t)b * rowsB * ND + h * HD;

    #pragma unroll
    for (int p = 0; p < 8; p++) {
        int idx = tid + p * 128;              // 1024 float4s
        int r = idx >> 4, c4 = (idx & 15) * 4;
        float4 qv = *reinterpret_cast<const float4*>(qb + (size_t)(t0 + r) * ND + c4);
        float4 bv = *reinterpret_cast<const float4*>(abias + h * HD + c4);
        int sc = c4 ^ (4 * (r & 7));
        unsigned* pq = &Qs[r * 64 + sc];
        pq[0] = f2tf32(qv.x + bv.x); pq[1] = f2tf32(qv.y + bv.y);
        pq[2] = f2tf32(qv.z + bv.z); pq[3] = f2tf32(qv.w + bv.w);
        int br = n0 + r;
        float4 kv = make_float4(0.f, 0.f, 0.f, 0.f);
        if (br < rowsB)
            kv = *reinterpret_cast<const float4*>(kb + (size_t)br * ND + c4);
        unsigned* pk = &Ks[r * 64 + sc];
        pk[0] = f2tf32(kv.x); pk[1] = f2tf32(kv.y);
        pk[2] = f2tf32(kv.z); pk[3] = f2tf32(kv.w);
    }
    __syncthreads();

    float acc[8][4];
    #pragma unroll
    for (int i = 0; i < 8; i++)
        #pragma unroll
        for (int j = 0; j < 4; j++) acc[i][j] = 0.f;

    #pragma unroll
    for (int ks = 0; ks < 8; ks++) {
        int colb = ks * 8 + cq;
        unsigned af[2][4], bf[4][2];
        #pragma unroll
        for (int i = 0; i < 2; i++) {
            int r = wm + i * 16 + g;
            af[i][0] = Qs[r * 64 + (colb ^ sz)];
            af[i][1] = Qs[(r + 8) * 64 + (colb ^ sz)];
            af[i][2] = Qs[r * 64 + ((colb + 4) ^ sz)];
            af[i][3] = Qs[(r + 8) * 64 + ((colb + 4) ^ sz)];
        }
        #pragma unroll
        for (int j = 0; j < 4; j++) {
            int r = wn + j * 8 + g;
            bf[j][0] = Ks[r * 64 + (colb ^ sz)];
            bf[j][1] = Ks[r * 64 + ((colb + 4) ^ sz)];
        }
        #pragma unroll
        for (int i = 0; i < 2; i++)
            #pragma unroll
            for (int j = 0; j < 4; j++)
                mma_tf32(acc[i * 4 + j], af[i], bf[j]);
    }

    float* Sz = S + (size_t)z * NT * NT;
    if (!REL) {
        #pragma unroll
        for (int i = 0; i < 2; i++) {
            #pragma unroll
            for (int j = 0; j < 4; j++) {
                int row = t0 + wm + i * 16 + g;
                int col = n0 + wn + j * 8 + 2 * cq;
                float* v = acc[i * 4 + j];
                Sz[(size_t)row * NT + col]           = v[0];
                Sz[(size_t)row * NT + col + 1]       = v[1];
                Sz[(size_t)(row + 8) * NT + col]     = v[2];
                Sz[(size_t)(row + 8) * NT + col + 1] = v[3];
            }
        }
    } else {
        #pragma unroll
        for (int i = 0; i < 2; i++) {
            #pragma unroll
            for (int j = 0; j < 4; j++) {
                float* v = acc[i * 4 + j];
                #pragma unroll
                for (int r = 0; r < 4; r++) {
                    int t = t0 + wm + i * 16 + g + ((r >> 1) ? 8 : 0);
                    int p = n0 + wn + j * 8 + 2 * cq + (r & 1);
                    int jj = p - (NT - 1) + t;
                    if (p < rowsB && jj >= 0 && jj < NT)
                        Sz[(size_t)t * NT + jj] += v[r];
                }
            }
        }
    }
}

// ---------------------------------------------------------------------------
// Softmax over rows of 512, scale 0.125 folded in. In place.
// ---------------------------------------------------------------------------
__global__ void softmax_kernel(float* __restrict__ S) {
    size_t row = blockIdx.x;
    float* r = S + row * NT;
    int tid = threadIdx.x;
    float v0 = r[tid] * 0.125f, v1 = r[tid + 256] * 0.125f;
    float m = fmaxf(v0, v1);
    #pragma unroll
    for (int o = 16; o > 0; o >>= 1) m = fmaxf(m, __shfl_xor_sync(0xffffffffu, m, o));
    __shared__ float shm[8];
    __shared__ float shs[8];
    int wid = tid >> 5, lane = tid & 31;
    if (lane == 0) shm[wid] = m;
    __syncthreads();
    float M = shm[0];
    #pragma unroll
    for (int i = 1; i < 8; i++) M = fmaxf(M, shm[i]);
    float e0 = __expf(v0 - M), e1 = __expf(v1 - M);
    float s = e0 + e1;
    #pragma unroll
    for (int o = 16; o > 0; o >>= 1) s += __shfl_xor_sync(0xffffffffu, s, o);
    if (lane == 0) shs[wid] = s;
    __syncthreads();
    float tot = 0.f;
    #pragma unroll
    for (int i = 0; i < 8; i++) tot += shs[i];
    float inv = 1.0f / tot;
    r[tid]       = e0 * inv;
    r[tid + 256] = e1 * inv;
}

// ---------------------------------------------------------------------------
// TF32 ctx GEMM: per (b,h): ctx[s, hd] = W[s,t] @ V[t, hd]
// Block 64(m) x 64(n=hd), 128 threads = 4 warps (2x2), warp tile 32x32,
// K loop BK=32, double-buffered.
// As (32-col rows): scol = col ^ (4*(row&7));  Bs n-major [k][64]:
// scol = n ^ (8*(k&3)) -> both conflict-free for frag loads and f4 fills.
// ---------------------------------------------------------------------------
__global__ __launch_bounds__(128) void ctx_tc(const float* __restrict__ S,
                                              const float* __restrict__ V,
                                              float* __restrict__ ctx) {
    int z = blockIdx.y, b = z >> 3, h = z & 7;
    int m0 = blockIdx.x * 64;
    __shared__ unsigned As[2][64 * 32];
    __shared__ unsigned Bs[2][32 * 64];
    int tid = threadIdx.x, lane = tid & 31, wid = tid >> 5;
    int g = lane >> 2, cq = lane & 3;
    int wm = (wid >> 1) * 32, wn = (wid & 1) * 32;
    const float* Sb = S + (size_t)z * NT * NT;
    const float* Vb = V + (size_t)b * NT * ND + h * HD;

    float acc[8][4];
    #pragma unroll
    for (int i = 0; i < 8; i++)
        #pragma unroll
        for (int j = 0; j < 4; j++) acc[i][j] = 0.f;

    float4 ra[4], rbv[4];
    auto gload = [&](int kc) {
        #pragma unroll
        for (int i = 0; i < 4; i++) {
            int idx = tid + i * 128;                // 512 f4 each
            int r = idx >> 3, c4 = (idx & 7) * 4;   // As: 64 rows x 8 f4
            ra[i] = *reinterpret_cast<const float4*>(Sb + (size_t)(m0 + r) * NT + kc * 32 + c4);
            int kr = idx >> 4, n4 = (idx & 15) * 4; // Bs: 32 rows x 16 f4
            rbv[i] = *reinterpret_cast<const float4*>(Vb + (size_t)(kc * 32 + kr) * ND + n4);
        }
    };
    auto sstore = [&](int buf) {
        #pragma unroll
        for (int i = 0; i < 4; i++) {
            int idx = tid + i * 128;
            int r = idx >> 3, c4 = (idx & 7) * 4;
            int sc = c4 ^ (4 * (r & 7));
            unsigned* pa = &As[buf][r * 32 + sc];
            pa[0] = f2tf32(ra[i].x); pa[1] = f2tf32(ra[i].y);
            pa[2] = f2tf32(ra[i].z); pa[3] = f2tf32(ra[i].w);
            int kr = idx >> 4, n4 = (idx & 15) * 4;
            int sc2 = n4 ^ (8 * (kr & 3));
            unsigned* pb = &Bs[buf][kr * 64 + sc2];
            pb[0] = f2tf32(rbv[i].x); pb[1] = f2tf32(rbv[i].y);
            pb[2] = f2tf32(rbv[i].z); pb[3] = f2tf32(rbv[i].w);
        }
    };
    auto compute = [&](int buf) {
        #pragma unroll
        for (int ks = 0; ks < 4; ks++) {
            int colb = ks * 8 + cq;
            unsigned af[2][4], bf[4][2];
            #pragma unroll
            for (int i = 0; i < 2; i++) {
                int r = wm + i * 16 + g;
                int sza = 4 * g;
                af[i][0] = As[buf][r * 32 + (colb ^ sza)];
                af[i][1] = As[buf][(r + 8) * 32 + (colb ^ sza)];
                af[i][2] = As[buf][r * 32 + ((colb + 4) ^ sza)];
                af[i][3] = As[buf][(r + 8) * 32 + ((colb + 4) ^ sza)];
            }
            #pragma unroll
            for (int j = 0; j < 4; j++) {
                int n = wn + j * 8 + g;
                int k0 = ks * 8 + cq;
                bf[j][0] = Bs[buf][k0 * 64 + (n ^ (8 * cq))];
                bf[j][1] = Bs[buf][(k0 + 4) * 64 + (n ^ (8 * cq))];
            }
            #pragma unroll
            for (int i = 0; i < 2; i++)
                #pragma unroll
                for (int j = 0; j < 4; j++)
                    mma_tf32(acc[i * 4 + j], af[i], bf[j]);
        }
    };

    gload(0);
    sstore(0);
    __syncthreads();
    for (int kc = 0; kc < 16; kc++) {
        if (kc < 15) gload(kc + 1);
        compute(kc & 1);
        if (kc < 15) sstore((kc + 1) & 1);
        __syncthreads();
    }

    #pragma unroll
    for (int i = 0; i < 2; i++) {
        #pragma unroll
        for (int j = 0; j < 4; j++) {
            int row = m0 + wm + i * 16 + g;
            int col = wn + j * 8 + 2 * cq;
            float* v = acc[i * 4 + j];
            float* dst0 = ctx + (size_t)(b * NT + row) * ND + h * HD + col;
            float* dst1 = ctx + (size_t)(b * NT + row + 8) * ND + h * HD + col;
            dst0[0] = v[0]; dst0[1] = v[1];
            dst1[0] = v[2]; dst1[1] = v[3];
        }
    }
}

// ---------------------------------------------------------------------------
extern "C" void kernel_launch(void* const* d_in, const int* in_sizes, int n_in,
                              void* d_out, int out_size) {
    const float* x    = (const float*)d_in[0];
    const float* pos  = (const float*)d_in[1];
    const float* ln_g = (const float*)d_in[2];
    const float* ln_b = (const float*)d_in[3];
    const float* Wq   = (const float*)d_in[4];
    const float* bq   = (const float*)d_in[5];
    const float* Wk   = (const float*)d_in[6];
    const float* bk   = (const float*)d_in[7];
    const float* Wv   = (const float*)d_in[8];
    const float* bv   = (const float*)d_in[9];
    const float* Wp   = (const float*)d_in[10];
    const float* bp   = (const float*)d_in[11];
    const float* cb   = (const float*)d_in[12];
    const float* pb   = (const float*)d_in[13];
    const float* Wo   = (const float*)d_in[14];
    const float* bo   = (const float*)d_in[15];
    float* out = (float*)d_out;

    float *xn, *q, *k, *v, *p, *S, *ctx;
    cudaGetSymbolAddress((void**)&xn,  g_xn);
    cudaGetSymbolAddress((void**)&q,   g_q);
    cudaGetSymbolAddress((void**)&k,   g_kk);
    cudaGetSymbolAddress((void**)&v,   g_v);
    cudaGetSymbolAddress((void**)&p,   g_pp);
    cudaGetSymbolAddress((void**)&S,   g_S);
    cudaGetSymbolAddress((void**)&ctx, g_ctx);

    // 1. LayerNorm
    ln_kernel<<<NB * NT, 256>>>(x, ln_g, ln_b, xn);

    // 2. Q/K/V projections  [8192,512] x [512,512]^T  (TF32 MMA)
    dim3 g1(4, (NB * NT) / 128);
    gemm_nt_tc<<<g1, 256>>>(xn, Wq, bq, q, NB * NT);
    gemm_nt_tc<<<g1, 256>>>(xn, Wk, bk, k, NB * NT);
    gemm_nt_tc<<<g1, 256>>>(xn, Wv, bv, v, NB * NT);

    // 3. P projection  [16368,512] x [512,512]^T
    dim3 gp(4, (NB * NP + 127) / 128);
    gemm_nt_tc<<<gp, 256>>>(pos, Wp, bp, p, NB * NP);

    // 4. Content scores: S[s,t] = (q+cb).k
    dim3 gc(NT / 64, NT / 64, NB * NH);
    attn_score_tc<false><<<gc, 128>>>(q, k, cb, S, NT);

    // 5. Pos scores with fused rel_shift scatter-add
    dim3 gr((NP + 63) / 64, NT / 64, NB * NH);
    attn_score_tc<true><<<gr, 128>>>(q, p, pb, S, NP);

    // 6. Softmax (scale folded)
    softmax_kernel<<<NB * NH * NT, 256>>>(S);

    // 7. ctx = W @ V
    dim3 gx(NT / 64, NB * NH);
    ctx_tc<<<gx, 128>>>(S, v, ctx);

    // 8. Output projection -> d_out
    gemm_nt_tc<<<g1, 256>>>(ctx, Wo, bo, out, NB * NT);
}

// round 6
// speedup vs baseline: 3.0545x; 1.6871x over previous
#include <cuda_runtime.h>

// ---------------------------------------------------------------------------
// Transformer-XL relative multi-head attention, TF32 tensor-core version with
// fused flash-style attention (no materialized score matrix).
// B=16, T=512, D=512, H=8, hd=64, P=2T-1=1023.
//
// rel_shift identity: shifted[b,h,t,j] = pos_score[b,h,t, (T-1)+j-t].
// For a 64x64 (t,j) tile the needed p rows form the band
//   [448 + j0 - t0, 448 + j0 - t0 + 126]  (always inside [0,1022]),
// and the gather index within the band is 63 + j_local - t_local.
// ---------------------------------------------------------------------------

#define NB 16
#define NT 512
#define ND 512
#define NH 8
#define HD 64
#define NP (2*NT - 1)   // 1023

__device__ float g_xn [NB*NT*ND];
__device__ float g_q  [NB*NT*ND];
__device__ float g_kk [NB*NT*ND];
__device__ float g_v  [NB*NT*ND];
__device__ float g_pp [NB*NP*ND];
__device__ float g_ctx[NB*NT*ND];

// ---------------------------------------------------------------------------
__device__ __forceinline__ unsigned f2tf32(float x) {
    unsigned u;
    asm("cvt.rna.tf32.f32 %0, %1;" : "=r"(u) : "f"(x));
    return u;
}

__device__ __forceinline__ void mma_tf32(float* d, const unsigned* a, const unsigned* b) {
    asm volatile(
        "mma.sync.aligned.m16n8k8.row.col.f32.tf32.tf32.f32 "
        "{%0,%1,%2,%3}, {%4,%5,%6,%7}, {%8,%9}, {%0,%1,%2,%3};"
        : "+f"(d[0]), "+f"(d[1]), "+f"(d[2]), "+f"(d[3])
        : "r"(a[0]), "r"(a[1]), "r"(a[2]), "r"(a[3]), "r"(b[0]), "r"(b[1]));
}

// ---------------------------------------------------------------------------
// LayerNorm
// ---------------------------------------------------------------------------
__global__ void ln_kernel(const float* __restrict__ x,
                          const float* __restrict__ gam,
                          const float* __restrict__ bet,
                          float* __restrict__ xn) {
    int row = blockIdx.x;
    int tid = threadIdx.x;
    const float* xr = x + (size_t)row * ND;
    float v0 = xr[tid], v1 = xr[tid + 256];
    float s = v0 + v1, ss = v0*v0 + v1*v1;
    #pragma unroll
    for (int o = 16; o > 0; o >>= 1) {
        s  += __shfl_down_sync(0xffffffffu, s,  o);
        ss += __shfl_down_sync(0xffffffffu, ss, o);
    }
    __shared__ float sh[16];
    __shared__ float smu, srs;
    int wid = tid >> 5, lane = tid & 31;
    if (lane == 0) { sh[wid] = s; sh[wid + 8] = ss; }
    __syncthreads();
    if (tid == 0) {
        float t1 = 0.f, t2 = 0.f;
        #pragma unroll
        for (int i = 0; i < 8; i++) { t1 += sh[i]; t2 += sh[i + 8]; }
        float mu  = t1 * (1.0f / ND);
        float var = t2 * (1.0f / ND) - mu * mu;
        smu = mu;
        srs = rsqrtf(var + 1e-5f);
    }
    __syncthreads();
    float mu = smu, rs = srs;
    float* xo = xn + (size_t)row * ND;
    xo[tid]       = (v0 - mu) * rs * gam[tid]       + bet[tid];
    xo[tid + 256] = (v1 - mu) * rs * gam[tid + 256] + bet[tid + 256];
}

// ---------------------------------------------------------------------------
// TF32 projection GEMM: C[M,512] = A[M,512] @ W[512,512]^T + bias
// (unchanged from previous round)
// ---------------------------------------------------------------------------
__global__ __launch_bounds__(256) void gemm_nt_tc(const float* __restrict__ A,
                                                  const float* __restrict__ W,
                                                  const float* __restrict__ bias,
                                                  float* __restrict__ C, int M) {
    __shared__ unsigned As[2][128 * 16];
    __shared__ unsigned Bs[2][128 * 16];
    const int tid = threadIdx.x, lane = tid & 31, wid = tid >> 5;
    const int g = lane >> 2, cq = lane & 3;
    const int wm = (wid >> 2) * 64, wn = (wid & 3) * 32;
    const int m0 = blockIdx.y * 128, n0 = blockIdx.x * 128;
    const int sza = 4 * ((g >> 1) & 3);

    float acc[16][4];
    #pragma unroll
    for (int i = 0; i < 16; i++)
        #pragma unroll
        for (int j = 0; j < 4; j++) acc[i][j] = 0.f;

    float4 ra[2], rb[2];

    auto gload = [&](int kc) {
        #pragma unroll
        for (int i = 0; i < 2; i++) {
            int idx = tid + i * 256;
            int r = idx >> 2, cc = (idx & 3) * 4;
            int arow = m0 + r;
            if (arow < M)
                ra[i] = *reinterpret_cast<const float4*>(A + (size_t)arow * 512 + kc * 16 + cc);
            else
                ra[i] = make_float4(0.f, 0.f, 0.f, 0.f);
            rb[i] = *reinterpret_cast<const float4*>(W + (size_t)(n0 + r) * 512 + kc * 16 + cc);
        }
    };
    auto sstore = [&](int buf) {
        #pragma unroll
        for (int i = 0; i < 2; i++) {
            int idx = tid + i * 256;
            int r = idx >> 2, cc = (idx & 3) * 4;
            int sc = cc ^ (4 * ((r >> 1) & 3));
            unsigned* pa = &As[buf][r * 16 + sc];
            pa[0] = f2tf32(ra[i].x); pa[1] = f2tf32(ra[i].y);
            pa[2] = f2tf32(ra[i].z); pa[3] = f2tf32(ra[i].w);
            unsigned* pb = &Bs[buf][r * 16 + sc];
            pb[0] = f2tf32(rb[i].x); pb[1] = f2tf32(rb[i].y);
            pb[2] = f2tf32(rb[i].z); pb[3] = f2tf32(rb[i].w);
        }
    };
    auto compute = [&](int buf) {
        #pragma unroll
        for (int ks = 0; ks < 2; ks++) {
            int colb = ks * 8 + cq;
            unsigned af[4][4], bf[4][2];
            #pragma unroll
            for (int i = 0; i < 4; i++) {
                int r = wm + i * 16 + g;
                af[i][0] = As[buf][r * 16 + (colb ^ sza)];
                af[i][1] = As[buf][(r + 8) * 16 + (colb ^ sza)];
                af[i][2] = As[buf][r * 16 + ((colb + 4) ^ sza)];
                af[i][3] = As[buf][(r + 8) * 16 + ((colb + 4) ^ sza)];
            }
            #pragma unroll
            for (int j = 0; j < 4; j++) {
                int r = wn + j * 8 + g;
                bf[j][0] = Bs[buf][r * 16 + (colb ^ sza)];
                bf[j][1] = Bs[buf][r * 16 + ((colb + 4) ^ sza)];
            }
            #pragma unroll
            for (int i = 0; i < 4; i++)
                #pragma unroll
                for (int j = 0; j < 4; j++)
                    mma_tf32(acc[i * 4 + j], af[i], bf[j]);
        }
    };

    gload(0);
    sstore(0);
    __syncthreads();
    for (int kc = 0; kc < 32; kc++) {
        if (kc < 31) gload(kc + 1);
        compute(kc & 1);
        if (kc < 31) sstore((kc + 1) & 1);
        __syncthreads();
    }

    #pragma unroll
    for (int i = 0; i < 4; i++) {
        int row = m0 + wm + i * 16 + g;
        #pragma unroll
        for (int j = 0; j < 4; j++) {
            int col = n0 + wn + j * 8 + 2 * cq;
            float b0 = __ldg(&bias[col]), b1 = __ldg(&bias[col + 1]);
            float* v = acc[i * 4 + j];
            if (row < M) {
                C[(size_t)row * 512 + col]     = v[0] + b0;
                C[(size_t)row * 512 + col + 1] = v[1] + b1;
            }
            if (row + 8 < M) {
                C[(size_t)(row + 8) * 512 + col]     = v[2] + b0;
                C[(size_t)(row + 8) * 512 + col + 1] = v[3] + b1;
            }
        }
    }
}

// ---------------------------------------------------------------------------
// Fused flash attention with relative-position band GEMM.
// Grid (8 t-tiles, B*H). 256 threads = 8 warps, warp grid 4(m) x 2(n),
// warp tile 16x32 over the 64-row x 64-col working tile.
//
// smem swizzles:
//   A-style [r][64]: col ^ (4*(r&7))         (uQc, uQp, uK, uB, uP)
//   V [k][64]:       n ^ (8*(k&3))           (uV; frag uses 8*cq)
//   fPS stride 136 -> bank = (7g+2cq+..)%32, conflict-free diagonal gather.
// ---------------------------------------------------------------------------
#define PS_STRIDE 136
#define FLASH_SMEM ((64*64*5 + 128*64) * 4 + 64*PS_STRIDE*4 + (64*3 + 128) * 4)

__global__ __launch_bounds__(256) void flash_attn(
    const float* __restrict__ Q, const float* __restrict__ K,
    const float* __restrict__ V, const float* __restrict__ P,
    const float* __restrict__ cb, const float* __restrict__ pb,
    float* __restrict__ ctx) {
    extern __shared__ char smraw[];
    unsigned* uQc = (unsigned*)smraw;
    unsigned* uQp = uQc + 64*64;
    unsigned* uK  = uQp + 64*64;
    unsigned* uV  = uK  + 64*64;
    unsigned* uP  = uV  + 64*64;
    unsigned* uB  = uP  + 64*64;          // 128 x 64 band
    float* fPS  = (float*)(uB + 128*64);  // 64 x PS_STRIDE
    float* fM   = fPS + 64*PS_STRIDE;
    float* fL   = fM + 64;
    float* fA   = fL + 64;
    float* fRed = fA + 64;                // [2][64]

    const int tid = threadIdx.x, lane = tid & 31, wid = tid >> 5;
    const int g = lane >> 2, cq = lane & 3;
    const int wm = (wid >> 1) * 16, wn = (wid & 1) * 32;
    const int t0 = blockIdx.x * 64;
    const int z = blockIdx.y, b = z >> 3, h = z & 7;
    const int sz = 4 * g;

    const float* Qb = Q + (size_t)b * NT * ND + h * HD;
    const float* Kb = K + (size_t)b * NT * ND + h * HD;
    const float* Vb = V + (size_t)b * NT * ND + h * HD;
    const float* Pb = P + (size_t)b * NP * ND + h * HD;

    // ---- load Q tile once; build qc = q+cb and qp = q+pb ----
    #pragma unroll
    for (int i = 0; i < 4; i++) {
        int idx = tid + i * 256;
        int r = idx >> 4, c4 = (idx & 15) * 4;
        float4 qv  = *reinterpret_cast<const float4*>(Qb + (size_t)(t0 + r) * ND + c4);
        float4 cbv = *reinterpret_cast<const float4*>(cb + h * HD + c4);
        float4 pbv = *reinterpret_cast<const float4*>(pb + h * HD + c4);
        int sc = c4 ^ (4 * (r & 7));
        uint4 qc = make_uint4(f2tf32(qv.x + cbv.x), f2tf32(qv.y + cbv.y),
                              f2tf32(qv.z + cbv.z), f2tf32(qv.w + cbv.w));
        *reinterpret_cast<uint4*>(&uQc[r * 64 + sc]) = qc;
        uint4 qp = make_uint4(f2tf32(qv.x + pbv.x), f2tf32(qv.y + pbv.y),
                              f2tf32(qv.z + pbv.z), f2tf32(qv.w + pbv.w));
        *reinterpret_cast<uint4*>(&uQp[r * 64 + sc]) = qp;
    }
    if (tid < 64) { fM[tid] = -1e30f; fL[tid] = 0.f; }

    float acc_o[4][4];
    #pragma unroll
    for (int j = 0; j < 4; j++)
        #pragma unroll
        for (int q4 = 0; q4 < 4; q4++) acc_o[j][q4] = 0.f;

    const int r0 = wm + g, r1 = wm + 8 + g;

    for (int jt = 0; jt < 8; jt++) {
        const int j0 = jt * 64;
        const int pbase = 448 + j0 - t0;   // band start; always in [0, 896]
        __syncthreads();                   // protect smem reuse vs prev MMA reads

        // ---- load K, V tiles ----
        #pragma unroll
        for (int i = 0; i < 4; i++) {
            int idx = tid + i * 256;
            int r = idx >> 4, c4 = (idx & 15) * 4;
            float4 kv = *reinterpret_cast<const float4*>(Kb + (size_t)(j0 + r) * ND + c4);
            int sc = c4 ^ (4 * (r & 7));
            *reinterpret_cast<uint4*>(&uK[r * 64 + sc]) =
                make_uint4(f2tf32(kv.x), f2tf32(kv.y), f2tf32(kv.z), f2tf32(kv.w));
            float4 vv = *reinterpret_cast<const float4*>(Vb + (size_t)(j0 + r) * ND + c4);
            int sv = c4 ^ (8 * (r & 3));
            *reinterpret_cast<uint4*>(&uV[r * 64 + sv]) =
                make_uint4(f2tf32(vv.x), f2tf32(vv.y), f2tf32(vv.z), f2tf32(vv.w));
        }
        // ---- load position band: rows pbase..pbase+126, row 127 zero ----
        #pragma unroll
        for (int i = 0; i < 8; i++) {
            int idx = tid + i * 256;
            int r = idx >> 4, c4 = (idx & 15) * 4;
            float4 bv = make_float4(0.f, 0.f, 0.f, 0.f);
            if (r < 127)
                bv = *reinterpret_cast<const float4*>(Pb + (size_t)(pbase + r) * ND + c4);
            int sc = c4 ^ (4 * (r & 7));
            *reinterpret_cast<uint4*>(&uB[r * 64 + sc]) =
                make_uint4(f2tf32(bv.x), f2tf32(bv.y), f2tf32(bv.z), f2tf32(bv.w));
        }
        __syncthreads();

        // ---- content MMA: acc_c = qc @ k^T ----
        float acc_c[4][4];
        #pragma unroll
        for (int j = 0; j < 4; j++)
            #pragma unroll
            for (int q4 = 0; q4 < 4; q4++) acc_c[j][q4] = 0.f;
        #pragma unroll
        for (int ks = 0; ks < 8; ks++) {
            int colb = ks * 8 + cq;
            unsigned af[4];
            af[0] = uQc[r0 * 64 + (colb ^ sz)];
            af[1] = uQc[r1 * 64 + (colb ^ sz)];
            af[2] = uQc[r0 * 64 + ((colb + 4) ^ sz)];
            af[3] = uQc[r1 * 64 + ((colb + 4) ^ sz)];
            #pragma unroll
            for (int j = 0; j < 4; j++) {
                int n = wn + j * 8 + g;
                unsigned bf[2] = { uK[n * 64 + (colb ^ sz)],
                                   uK[n * 64 + ((colb + 4) ^ sz)] };
                mma_tf32(acc_c[j], af, bf);
            }
        }

        // ---- band MMA: PS[t, band] = qp @ p_band^T, 2 passes of n=64 ----
        #pragma unroll
        for (int pass = 0; pass < 2; pass++) {
            float acc_p[4][4];
            #pragma unroll
            for (int j = 0; j < 4; j++)
                #pragma unroll
                for (int q4 = 0; q4 < 4; q4++) acc_p[j][q4] = 0.f;
            #pragma unroll
            for (int ks = 0; ks < 8; ks++) {
                int colb = ks * 8 + cq;
                unsigned af[4];
                af[0] = uQp[r0 * 64 + (colb ^ sz)];
                af[1] = uQp[r1 * 64 + (colb ^ sz)];
                af[2] = uQp[r0 * 64 + ((colb + 4) ^ sz)];
                af[3] = uQp[r1 * 64 + ((colb + 4) ^ sz)];
                #pragma unroll
                for (int j = 0; j < 4; j++) {
                    int n = pass * 64 + wn + j * 8 + g;
                    unsigned bf[2] = { uB[n * 64 + (colb ^ sz)],
                                       uB[n * 64 + ((colb + 4) ^ sz)] };
                    mma_tf32(acc_p[j], af, bf);
                }
            }
            #pragma unroll
            for (int j = 0; j < 4; j++) {
                int c = pass * 64 + wn + j * 8 + 2 * cq;
                fPS[r0 * PS_STRIDE + c]     = acc_p[j][0];
                fPS[r0 * PS_STRIDE + c + 1] = acc_p[j][1];
                fPS[r1 * PS_STRIDE + c]     = acc_p[j][2];
                fPS[r1 * PS_STRIDE + c + 1] = acc_p[j][3];
            }
        }
        __syncthreads();

        // ---- gather band diagonal, combine, scale; row maxima ----
        float s[4][4];
        float rmax0 = -1e30f, rmax1 = -1e30f;
        #pragma unroll
        for (int j = 0; j < 4; j++) {
            int c = wn + j * 8 + 2 * cq;
            s[j][0] = (acc_c[j][0] + fPS[r0 * PS_STRIDE + (63 + c     - r0)]) * 0.125f;
            s[j][1] = (acc_c[j][1] + fPS[r0 * PS_STRIDE + (63 + c + 1 - r0)]) * 0.125f;
            s[j][2] = (acc_c[j][2] + fPS[r1 * PS_STRIDE + (63 + c     - r1)]) * 0.125f;
            s[j][3] = (acc_c[j][3] + fPS[r1 * PS_STRIDE + (63 + c + 1 - r1)]) * 0.125f;
            rmax0 = fmaxf(rmax0, fmaxf(s[j][0], s[j][1]));
            rmax1 = fmaxf(rmax1, fmaxf(s[j][2], s[j][3]));
        }
        rmax0 = fmaxf(rmax0, __shfl_xor_sync(0xffffffffu, rmax0, 1));
        rmax0 = fmaxf(rmax0, __shfl_xor_sync(0xffffffffu, rmax0, 2));
        rmax1 = fmaxf(rmax1, __shfl_xor_sync(0xffffffffu, rmax1, 1));
        rmax1 = fmaxf(rmax1, __shfl_xor_sync(0xffffffffu, rmax1, 2));
        if (cq == 0) {
            fRed[(wid & 1) * 64 + r0] = rmax0;
            fRed[(wid & 1) * 64 + r1] = rmax1;
        }
        __syncthreads();
        if (tid < 64) {
            float mo = fM[tid];
            float mn = fmaxf(mo, fmaxf(fRed[tid], fRed[64 + tid]));
            fM[tid] = mn;
            fA[tid] = __expf(mo - mn);
        }
        __syncthreads();

        // ---- exponentials, store P (tf32), rescale O, row sums ----
        float mn0 = fM[r0], mn1 = fM[r1];
        float al0 = fA[r0], al1 = fA[r1];
        float rsum0 = 0.f, rsum1 = 0.f;
        #pragma unroll
        for (int j = 0; j < 4; j++) {
            float p00 = __expf(s[j][0] - mn0), p01 = __expf(s[j][1] - mn0);
            float p10 = __expf(s[j][2] - mn1), p11 = __expf(s[j][3] - mn1);
            rsum0 += p00 + p01;
            rsum1 += p10 + p11;
            int c = wn + j * 8 + 2 * cq;
            uP[r0 * 64 + ( c      ^ sz)] = f2tf32(p00);
            uP[r0 * 64 + ((c + 1) ^ sz)] = f2tf32(p01);
            uP[r1 * 64 + ( c      ^ sz)] = f2tf32(p10);
            uP[r1 * 64 + ((c + 1) ^ sz)] = f2tf32(p11);
            acc_o[j][0] *= al0; acc_o[j][1] *= al0;
            acc_o[j][2] *= al1; acc_o[j][3] *= al1;
        }
        rsum0 += __shfl_xor_sync(0xffffffffu, rsum0, 1);
        rsum0 += __shfl_xor_sync(0xffffffffu, rsum0, 2);
        rsum1 += __shfl_xor_sync(0xffffffffu, rsum1, 1);
        rsum1 += __shfl_xor_sync(0xffffffffu, rsum1, 2);
        if (cq == 0) {
            fRed[(wid & 1) * 64 + r0] = rsum0;
            fRed[(wid & 1) * 64 + r1] = rsum1;
        }
        __syncthreads();
        if (tid < 64) fL[tid] = fL[tid] * fA[tid] + fRed[tid] + fRed[64 + tid];

        // ---- O += P @ V ----
        #pragma unroll
        for (int ks = 0; ks < 8; ks++) {
            int colb = ks * 8 + cq;
            unsigned af[4];
            af[0] = uP[r0 * 64 + (colb ^ sz)];
            af[1] = uP[r1 * 64 + (colb ^ sz)];
            af[2] = uP[r0 * 64 + ((colb + 4) ^ sz)];
            af[3] = uP[r1 * 64 + ((colb + 4) ^ sz)];
            #pragma unroll
            for (int j = 0; j < 4; j++) {
                int n = wn + j * 8 + g;
                unsigned bf[2] = { uV[colb * 64 + (n ^ (8 * cq))],
                                   uV[(colb + 4) * 64 + (n ^ (8 * cq))] };
                mma_tf32(acc_o[j], af, bf);
            }
        }
    }

    __syncthreads();   // fL final before epilogue reads
    float il0 = 1.0f / fL[r0], il1 = 1.0f / fL[r1];
    #pragma unroll
    for (int j = 0; j < 4; j++) {
        int c = wn + j * 8 + 2 * cq;
        float* d0 = ctx + ((size_t)(b * NT + t0 + r0)) * ND + h * HD + c;
        float* d1 = ctx + ((size_t)(b * NT + t0 + r1)) * ND + h * HD + c;
        d0[0] = acc_o[j][0] * il0; d0[1] = acc_o[j][1] * il0;
        d1[0] = acc_o[j][2] * il1; d1[1] = acc_o[j][3] * il1;
    }
}

// ---------------------------------------------------------------------------
extern "C" void kernel_launch(void* const* d_in, const int* in_sizes, int n_in,
                              void* d_out, int out_size) {
    const float* x    = (const float*)d_in[0];
    const float* pos  = (const float*)d_in[1];
    const float* ln_g = (const float*)d_in[2];
    const float* ln_b = (const float*)d_in[3];
    const float* Wq   = (const float*)d_in[4];
    const float* bq   = (const float*)d_in[5];
    const float* Wk   = (const float*)d_in[6];
    const float* bk   = (const float*)d_in[7];
    const float* Wv   = (const float*)d_in[8];
    const float* bv   = (const float*)d_in[9];
    const float* Wp   = (const float*)d_in[10];
    const float* bp   = (const float*)d_in[11];
    const float* cb   = (const float*)d_in[12];
    const float* pb   = (const float*)d_in[13];
    const float* Wo   = (const float*)d_in[14];
    const float* bo   = (const float*)d_in[15];
    float* out = (float*)d_out;

    float *xn, *q, *k, *v, *p, *ctx;
    cudaGetSymbolAddress((void**)&xn,  g_xn);
    cudaGetSymbolAddress((void**)&q,   g_q);
    cudaGetSymbolAddress((void**)&k,   g_kk);
    cudaGetSymbolAddress((void**)&v,   g_v);
    cudaGetSymbolAddress((void**)&p,   g_pp);
    cudaGetSymbolAddress((void**)&ctx, g_ctx);

    cudaFuncSetAttribute(flash_attn, cudaFuncAttributeMaxDynamicSharedMemorySize,
                         FLASH_SMEM);

    // 1. LayerNorm
    ln_kernel<<<NB * NT, 256>>>(x, ln_g, ln_b, xn);

    // 2. Q/K/V projections
    dim3 g1(4, (NB * NT) / 128);
    gemm_nt_tc<<<g1, 256>>>(xn, Wq, bq, q, NB * NT);
    gemm_nt_tc<<<g1, 256>>>(xn, Wk, bk, k, NB * NT);
    gemm_nt_tc<<<g1, 256>>>(xn, Wv, bv, v, NB * NT);

    // 3. P projection
    dim3 gp(4, (NB * NP + 127) / 128);
    gemm_nt_tc<<<gp, 256>>>(pos, Wp, bp, p, NB * NP);

    // 4. Fused attention (content + rel-pos band + online softmax + P@V)
    dim3 ga(NT / 64, NB * NH);
    flash_attn<<<ga, 256, FLASH_SMEM>>>(q, k, v, p, cb, pb, ctx);

    // 5. Output projection -> d_out
    gemm_nt_tc<<<g1, 256>>>(ctx, Wo, bo, out, NB * NT);
}

// round 9
// speedup vs baseline: 3.2997x; 1.0803x over previous
#include <cuda_runtime.h>

// ---------------------------------------------------------------------------
// Transformer-XL relative multi-head attention, TF32 tensor cores, fused
// flash attention. B=16, T=512, D=512, H=8, hd=64, P=2T-1=1023.
//
// All GEMM operands are pre-rounded to tf32-representable f32 in gmem
// (weights/pos via prep kernel, activations at producer epilogues), so GEMM
// hot loops do raw cp.async copies and feed bits straight to mma.sync.
// ---------------------------------------------------------------------------

#define NB 16
#define NT 512
#define ND 512
#define NH 8
#define HD 64
#define NP (2*NT - 1)   // 1023

__device__ float g_xn  [NB*NT*ND];
__device__ float g_q   [NB*NT*ND];
__device__ float g_kk  [NB*NT*ND];
__device__ float g_v   [NB*NT*ND];
__device__ float g_pp  [NB*NP*ND];
__device__ float g_ctx [NB*NT*ND];
__device__ float g_wr  [5 * ND * ND];       // rounded Wq,Wk,Wv,Wp,Wo
__device__ float g_posr[NB*NP*ND];          // rounded pos_emb

// ---------------------------------------------------------------------------
__device__ __forceinline__ unsigned f2tf32(float x) {
    unsigned u;
    asm("cvt.rna.tf32.f32 %0, %1;" : "=r"(u) : "f"(x));
    return u;
}
__device__ __forceinline__ float roundtf(float x) { return __uint_as_float(f2tf32(x)); }

__device__ __forceinline__ void mma_tf32(float* d, const unsigned* a, const unsigned* b) {
    asm volatile(
        "mma.sync.aligned.m16n8k8.row.col.f32.tf32.tf32.f32 "
        "{%0,%1,%2,%3}, {%4,%5,%6,%7}, {%8,%9}, {%0,%1,%2,%3};"
        : "+f"(d[0]), "+f"(d[1]), "+f"(d[2]), "+f"(d[3])
        : "r"(a[0]), "r"(a[1]), "r"(a[2]), "r"(a[3]), "r"(b[0]), "r"(b[1]));
}

__device__ __forceinline__ unsigned smaddr(const void* p) {
    return (unsigned)__cvta_generic_to_shared(p);
}
#define CP16(dst, src, pred) \
    asm volatile("cp.async.cg.shared.global [%0], [%1], 16, %2;" \
                 :: "r"(dst), "l"(src), "r"((pred) ? 16 : 0))
#define CP_COMMIT() asm volatile("cp.async.commit_group;")
#define CP_WAIT2()  asm volatile("cp.async.wait_group 2;")

// ---------------------------------------------------------------------------
// Prep: round weights + pos_emb to tf32-representable f32
// ---------------------------------------------------------------------------
struct RoundSet { const float* src[6]; float* dst[6]; int n4[6]; };

__global__ void round_copy(RoundSet rs) {
    int z = blockIdx.y;
    int n4 = rs.n4[z];
    const float4* s = (const float4*)rs.src[z];
    float4* d = (float4*)rs.dst[z];
    for (int i = blockIdx.x * blockDim.x + threadIdx.x; i < n4;
         i += gridDim.x * blockDim.x) {
        float4 v = s[i];
        d[i] = make_float4(roundtf(v.x), roundtf(v.y), roundtf(v.z), roundtf(v.w));
    }
}

// ---------------------------------------------------------------------------
// LayerNorm (writes tf32-rounded output)
// ---------------------------------------------------------------------------
__global__ void ln_kernel(const float* __restrict__ x,
                          const float* __restrict__ gam,
                          const float* __restrict__ bet,
                          float* __restrict__ xn) {
    int row = blockIdx.x;
    int tid = threadIdx.x;
    const float* xr = x + (size_t)row * ND;
    float v0 = xr[tid], v1 = xr[tid + 256];
    float s = v0 + v1, ss = v0*v0 + v1*v1;
    #pragma unroll
    for (int o = 16; o > 0; o >>= 1) {
        s  += __shfl_down_sync(0xffffffffu, s,  o);
        ss += __shfl_down_sync(0xffffffffu, ss, o);
    }
    __shared__ float sh[16];
    __shared__ float smu, srs;
    int wid = tid >> 5, lane = tid & 31;
    if (lane == 0) { sh[wid] = s; sh[wid + 8] = ss; }
    __syncthreads();
    if (tid == 0) {
        float t1 = 0.f, t2 = 0.f;
        #pragma unroll
        for (int i = 0; i < 8; i++) { t1 += sh[i]; t2 += sh[i + 8]; }
        float mu  = t1 * (1.0f / ND);
        float var = t2 * (1.0f / ND) - mu * mu;
        smu = mu;
        srs = rsqrtf(var + 1e-5f);
    }
    __syncthreads();
    float mu = smu, rs = srs;
    float* xo = xn + (size_t)row * ND;
    xo[tid]       = roundtf((v0 - mu) * rs * gam[tid]       + bet[tid]);
    xo[tid + 256] = roundtf((v1 - mu) * rs * gam[tid + 256] + bet[tid + 256]);
}

// ---------------------------------------------------------------------------
// TF32 GEMM core: C[M,512] = A[M,512] @ W[512,512]^T + bias.
// Operands pre-rounded in gmem. 128x128 tile, BK=16, 4-stage cp.async
// pipeline, 256 threads = 8 warps (2m x 4n), warp tile 64x32.
// Smem swizzle: sc = cc ^ (4*((r>>1)&3)); (r+64) keeps same swizzle.
// ---------------------------------------------------------------------------
template<bool ROUND>
__device__ __forceinline__ void gemm_core(const float* __restrict__ A,
                                          const float* __restrict__ W,
                                          const float* __restrict__ bias,
                                          float* __restrict__ C, int M,
                                          int m0, int n0,
                                          unsigned* sA, unsigned* sB) {
    const int tid = threadIdx.x, lane = tid & 31, wid = tid >> 5;
    const int g = lane >> 2, cq = lane & 3;
    const int wm = (wid >> 2) * 64, wn = (wid & 3) * 32;
    const int sza = 4 * ((g >> 1) & 3);

    // copy geometry: thread covers rows r, r+64 at cols [cc, cc+4)
    const int r  = tid >> 2;
    const int cc = (tid & 3) * 4;
    const int sc = cc ^ (4 * ((r >> 1) & 3));
    const int e0 = r * 16 + sc, e1 = (r + 64) * 16 + sc;
    const unsigned aB = smaddr(sA), bB = smaddr(sB);

    const int ar0 = m0 + r, ar1 = m0 + r + 64;
    const float* a0 = A + (size_t)(ar0 < M ? ar0 : 0) * 512 + cc;
    const float* a1 = A + (size_t)(ar1 < M ? ar1 : 0) * 512 + cc;
    const float* w0 = W + (size_t)(n0 + r) * 512 + cc;
    const float* w1 = W + (size_t)(n0 + r + 64) * 512 + cc;
    const bool p0 = ar0 < M, p1 = ar1 < M;

    float acc[16][4];
    #pragma unroll
    for (int i = 0; i < 16; i++)
        #pragma unroll
        for (int j = 0; j < 4; j++) acc[i][j] = 0.f;

    auto issue = [&](int stage, int kc) {
        unsigned ab = aB + stage * 8192, bb = bB + stage * 8192;
        int ko = kc * 16;
        CP16(ab + e0 * 4, a0 + ko, p0);
        CP16(ab + e1 * 4, a1 + ko, p1);
        CP16(bb + e0 * 4, w0 + ko, true);
        CP16(bb + e1 * 4, w1 + ko, true);
    };
    auto compute = [&](int stage) {
        const unsigned* As = sA + stage * 2048;
        const unsigned* Bs = sB + stage * 2048;
        #pragma unroll
        for (int ks = 0; ks < 2; ks++) {
            int colb = ks * 8 + cq;
            unsigned af[4][4], bf[4][2];
            #pragma unroll
            for (int i = 0; i < 4; i++) {
                int rr = wm + i * 16 + g;
                af[i][0] = As[rr * 16 + (colb ^ sza)];
                af[i][1] = As[(rr + 8) * 16 + (colb ^ sza)];
                af[i][2] = As[rr * 16 + ((colb + 4) ^ sza)];
                af[i][3] = As[(rr + 8) * 16 + ((colb + 4) ^ sza)];
            }
            #pragma unroll
            for (int j = 0; j < 4; j++) {
                int rr = wn + j * 8 + g;
                bf[j][0] = Bs[rr * 16 + (colb ^ sza)];
                bf[j][1] = Bs[rr * 16 + ((colb + 4) ^ sza)];
            }
            #pragma unroll
            for (int i = 0; i < 4; i++)
                #pragma unroll
                for (int j = 0; j < 4; j++)
                    mma_tf32(acc[i * 4 + j], af[i], bf[j]);
        }
    };

    issue(0, 0); CP_COMMIT();
    issue(1, 1); CP_COMMIT();
    issue(2, 2); CP_COMMIT();
    for (int kc = 0; kc < 32; kc++) {
        CP_WAIT2();
        __syncthreads();
        if (kc + 3 < 32) issue((kc + 3) & 3, kc + 3);
        CP_COMMIT();
        compute(kc & 3);
    }

    #pragma unroll
    for (int i = 0; i < 4; i++) {
        int row = m0 + wm + i * 16 + g;
        #pragma unroll
        for (int j = 0; j < 4; j++) {
            int col = n0 + wn + j * 8 + 2 * cq;
            float b0 = __ldg(&bias[col]), b1 = __ldg(&bias[col + 1]);
            float* v = acc[i * 4 + j];
            if (row < M) {
                float o0 = v[0] + b0, o1 = v[1] + b1;
                C[(size_t)row * 512 + col]     = ROUND ? roundtf(o0) : o0;
                C[(size_t)row * 512 + col + 1] = ROUND ? roundtf(o1) : o1;
            }
            if (row + 8 < M) {
                float o0 = v[2] + b0, o1 = v[3] + b1;
                C[(size_t)(row + 8) * 512 + col]     = ROUND ? roundtf(o0) : o0;
                C[(size_t)(row + 8) * 512 + col + 1] = ROUND ? roundtf(o1) : o1;
            }
        }
    }
}

struct ProjSet {
    const float* A[4]; const float* W[4]; const float* bias[4];
    float* C[4]; int M[4];
};

// Batched Q/K/V/P projections: grid (4, 128, 4), z selects GEMM.
__global__ __launch_bounds__(256, 2) void proj_batched(ProjSet ps) {
    extern __shared__ unsigned gsm[];
    int z = blockIdx.z;
    int M = ps.M[z];
    int m0 = blockIdx.y * 128;
    if (m0 >= M) return;
    gemm_core<true>(ps.A[z], ps.W[z], ps.bias[z], ps.C[z], M,
                    m0, blockIdx.x * 128, gsm, gsm + 4 * 2048);
}

// Output projection (unrounded output)
__global__ __launch_bounds__(256, 2) void gemm_out(const float* __restrict__ A,
                                                   const float* __restrict__ W,
                                                   const float* __restrict__ bias,
                                                   float* __restrict__ C, int M) {
    extern __shared__ unsigned gsm[];
    gemm_core<false>(A, W, bias, C, M, blockIdx.y * 128, blockIdx.x * 128,
                     gsm, gsm + 4 * 2048);
}

// ---------------------------------------------------------------------------
// Fused flash attention with relative-position band GEMM.
// Inputs q/k/v/p are pre-rounded -> tile loads are raw bit copies.
// rel_shift: band rows [448+j0-t0 .. +126], gather index 63 + j - t.
// ---------------------------------------------------------------------------
#define PS_STRIDE 136
#define FLASH_SMEM ((64*64*5 + 128*64) * 4 + 64*PS_STRIDE*4 + (64*3 + 128) * 4)

__global__ __launch_bounds__(256) void flash_attn(
    const float* __restrict__ Q, const float* __restrict__ K,
    const float* __restrict__ V, const float* __restrict__ P,
    const float* __restrict__ cb, const float* __restrict__ pb,
    float* __restrict__ ctx) {
    extern __shared__ char smraw[];
    unsigned* uQc = (unsigned*)smraw;
    unsigned* uQp = uQc + 64*64;
    unsigned* uK  = uQp + 64*64;
    unsigned* uV  = uK  + 64*64;
    unsigned* uP  = uV  + 64*64;
    unsigned* uB  = uP  + 64*64;          // 128 x 64 band
    float* fPS  = (float*)(uB + 128*64);  // 64 x PS_STRIDE
    float* fM   = fPS + 64*PS_STRIDE;
    float* fL   = fM + 64;
    float* fA   = fL + 64;
    float* fRed = fA + 64;                // [2][64]

    const int tid = threadIdx.x, lane = tid & 31, wid = tid >> 5;
    const int g = lane >> 2, cq = lane & 3;
    const int wm = (wid >> 1) * 16, wn = (wid & 1) * 32;
    const int t0 = blockIdx.x * 64;
    const int z = blockIdx.y, b = z >> 3, h = z & 7;
    const int sz = 4 * g;

    const float* Qb = Q + (size_t)b * NT * ND + h * HD;
    const float* Kb = K + (size_t)b * NT * ND + h * HD;
    const float* Vb = V + (size_t)b * NT * ND + h * HD;
    const float* Pb = P + (size_t)b * NP * ND + h * HD;

    // ---- Q tile once: qc = q+cb, qp = q+pb (cvt needed: bias is raw) ----
    #pragma unroll
    for (int i = 0; i < 4; i++) {
        int idx = tid + i * 256;
        int r = idx >> 4, c4 = (idx & 15) * 4;
        float4 qv  = *reinterpret_cast<const float4*>(Qb + (size_t)(t0 + r) * ND + c4);
        float4 cbv = *reinterpret_cast<const float4*>(cb + h * HD + c4);
        float4 pbv = *reinterpret_cast<const float4*>(pb + h * HD + c4);
        int sc = c4 ^ (4 * (r & 7));
        *reinterpret_cast<uint4*>(&uQc[r * 64 + sc]) =
            make_uint4(f2tf32(qv.x + cbv.x), f2tf32(qv.y + cbv.y),
                       f2tf32(qv.z + cbv.z), f2tf32(qv.w + cbv.w));
        *reinterpret_cast<uint4*>(&uQp[r * 64 + sc]) =
            make_uint4(f2tf32(qv.x + pbv.x), f2tf32(qv.y + pbv.y),
                       f2tf32(qv.z + pbv.z), f2tf32(qv.w + pbv.w));
    }
    if (tid < 64) { fM[tid] = -1e30f; fL[tid] = 0.f; }

    float acc_o[4][4];
    #pragma unroll
    for (int j = 0; j < 4; j++)
        #pragma unroll
        for (int q4 = 0; q4 < 4; q4++) acc_o[j][q4] = 0.f;

    const int r0 = wm + g, r1 = wm + 8 + g;

    for (int jt = 0; jt < 8; jt++) {
        const int j0 = jt * 64;
        const int pbase = 448 + j0 - t0;
        __syncthreads();

        // ---- K, V tiles: raw copies (pre-rounded) ----
        #pragma unroll
        for (int i = 0; i < 4; i++) {
            int idx = tid + i * 256;
            int r = idx >> 4, c4 = (idx & 15) * 4;
            uint4 kv = *reinterpret_cast<const uint4*>(Kb + (size_t)(j0 + r) * ND + c4);
            *reinterpret_cast<uint4*>(&uK[r * 64 + (c4 ^ (4 * (r & 7)))]) = kv;
            uint4 vv = *reinterpret_cast<const uint4*>(Vb + (size_t)(j0 + r) * ND + c4);
            *reinterpret_cast<uint4*>(&uV[r * 64 + (c4 ^ (8 * (r & 3)))]) = vv;
        }
        // ---- band: rows pbase..pbase+126, row 127 zero ----
        #pragma unroll
        for (int i = 0; i < 8; i++) {
            int idx = tid + i * 256;
            int r = idx >> 4, c4 = (idx & 15) * 4;
            uint4 bv = make_uint4(0u, 0u, 0u, 0u);
            if (r < 127)
                bv = *reinterpret_cast<const uint4*>(Pb + (size_t)(pbase + r) * ND + c4);
            *reinterpret_cast<uint4*>(&uB[r * 64 + (c4 ^ (4 * (r & 7)))]) = bv;
        }
        __syncthreads();

        // ---- content MMA ----
        float acc_c[4][4];
        #pragma unroll
        for (int j = 0; j < 4; j++)
            #pragma unroll
            for (int q4 = 0; q4 < 4; q4++) acc_c[j][q4] = 0.f;
        #pragma unroll
        for (int ks = 0; ks < 8; ks++) {
            int colb = ks * 8 + cq;
            unsigned af[4];
            af[0] = uQc[r0 * 64 + (colb ^ sz)];
            af[1] = uQc[r1 * 64 + (colb ^ sz)];
            af[2] = uQc[r0 * 64 + ((colb + 4) ^ sz)];
            af[3] = uQc[r1 * 64 + ((colb + 4) ^ sz)];
            #pragma unroll
            for (int j = 0; j < 4; j++) {
                int n = wn + j * 8 + g;
                unsigned bf[2] = { uK[n * 64 + (colb ^ sz)],
                                   uK[n * 64 + ((colb + 4) ^ sz)] };
                mma_tf32(acc_c[j], af, bf);
            }
        }

        // ---- band MMA, 2 passes ----
        #pragma unroll
        for (int pass = 0; pass < 2; pass++) {
            float acc_p[4][4];
            #pragma unroll
            for (int j = 0; j < 4; j++)
                #pragma unroll
                for (int q4 = 0; q4 < 4; q4++) acc_p[j][q4] = 0.f;
            #pragma unroll
            for (int ks = 0; ks < 8; ks++) {
                int colb = ks * 8 + cq;
                unsigned af[4];
                af[0] = uQp[r0 * 64 + (colb ^ sz)];
                af[1] = uQp[r1 * 64 + (colb ^ sz)];
                af[2] = uQp[r0 * 64 + ((colb + 4) ^ sz)];
                af[3] = uQp[r1 * 64 + ((colb + 4) ^ sz)];
                #pragma unroll
                for (int j = 0; j < 4; j++) {
                    int n = pass * 64 + wn + j * 8 + g;
                    unsigned bf[2] = { uB[n * 64 + (colb ^ sz)],
                                       uB[n * 64 + ((colb + 4) ^ sz)] };
                    mma_tf32(acc_p[j], af, bf);
                }
            }
            #pragma unroll
            for (int j = 0; j < 4; j++) {
                int c = pass * 64 + wn + j * 8 + 2 * cq;
                fPS[r0 * PS_STRIDE + c]     = acc_p[j][0];
                fPS[r0 * PS_STRIDE + c + 1] = acc_p[j][1];
                fPS[r1 * PS_STRIDE + c]     = acc_p[j][2];
                fPS[r1 * PS_STRIDE + c + 1] = acc_p[j][3];
            }
        }
        __syncthreads();

        // ---- gather diagonal, combine, row maxima ----
        float s[4][4];
        float rmax0 = -1e30f, rmax1 = -1e30f;
        #pragma unroll
        for (int j = 0; j < 4; j++) {
            int c = wn + j * 8 + 2 * cq;
            s[j][0] = (acc_c[j][0] + fPS[r0 * PS_STRIDE + (63 + c     - r0)]) * 0.125f;
            s[j][1] = (acc_c[j][1] + fPS[r0 * PS_STRIDE + (63 + c + 1 - r0)]) * 0.125f;
            s[j][2] = (acc_c[j][2] + fPS[r1 * PS_STRIDE + (63 + c     - r1)]) * 0.125f;
            s[j][3] = (acc_c[j][3] + fPS[r1 * PS_STRIDE + (63 + c + 1 - r1)]) * 0.125f;
            rmax0 = fmaxf(rmax0, fmaxf(s[j][0], s[j][1]));
            rmax1 = fmaxf(rmax1, fmaxf(s[j][2], s[j][3]));
        }
        rmax0 = fmaxf(rmax0, __shfl_xor_sync(0xffffffffu, rmax0, 1));
        rmax0 = fmaxf(rmax0, __shfl_xor_sync(0xffffffffu, rmax0, 2));
        rmax1 = fmaxf(rmax1, __shfl_xor_sync(0xffffffffu, rmax1, 1));
        rmax1 = fmaxf(rmax1, __shfl_xor_sync(0xffffffffu, rmax1, 2));
        if (cq == 0) {
            fRed[(wid & 1) * 64 + r0] = rmax0;
            fRed[(wid & 1) * 64 + r1] = rmax1;
        }
        __syncthreads();
        if (tid < 64) {
            float mo = fM[tid];
            float mn = fmaxf(mo, fmaxf(fRed[tid], fRed[64 + tid]));
            fM[tid] = mn;
            fA[tid] = __expf(mo - mn);
        }
        __syncthreads();

        // ---- exp, store P (tf32), rescale O, row sums ----
        float mn0 = fM[r0], mn1 = fM[r1];
        float al0 = fA[r0], al1 = fA[r1];
        float rsum0 = 0.f, rsum1 = 0.f;
        #pragma unroll
        for (int j = 0; j < 4; j++) {
            float p00 = __expf(s[j][0] - mn0), p01 = __expf(s[j][1] - mn0);
            float p10 = __expf(s[j][2] - mn1), p11 = __expf(s[j][3] - mn1);
            rsum0 += p00 + p01;
            rsum1 += p10 + p11;
            int c = wn + j * 8 + 2 * cq;
            uP[r0 * 64 + ( c      ^ sz)] = f2tf32(p00);
            uP[r0 * 64 + ((c + 1) ^ sz)] = f2tf32(p01);
            uP[r1 * 64 + ( c      ^ sz)] = f2tf32(p10);
            uP[r1 * 64 + ((c + 1) ^ sz)] = f2tf32(p11);
            acc_o[j][0] *= al0; acc_o[j][1] *= al0;
            acc_o[j][2] *= al1; acc_o[j][3] *= al1;
        }
        rsum0 += __shfl_xor_sync(0xffffffffu, rsum0, 1);
        rsum0 += __shfl_xor_sync(0xffffffffu, rsum0, 2);
        rsum1 += __shfl_xor_sync(0xffffffffu, rsum1, 1);
        rsum1 += __shfl_xor_sync(0xffffffffu, rsum1, 2);
        if (cq == 0) {
            fRed[(wid & 1) * 64 + r0] = rsum0;
            fRed[(wid & 1) * 64 + r1] = rsum1;
        }
        __syncthreads();
        if (tid < 64) fL[tid] = fL[tid] * fA[tid] + fRed[tid] + fRed[64 + tid];

        // ---- O += P @ V ----
        #pragma unroll
        for (int ks = 0; ks < 8; ks++) {
            int colb = ks * 8 + cq;
            unsigned af[4];
            af[0] = uP[r0 * 64 + (colb ^ sz)];
            af[1] = uP[r1 * 64 + (colb ^ sz)];
            af[2] = uP[r0 * 64 + ((colb + 4) ^ sz)];
            af[3] = uP[r1 * 64 + ((colb + 4) ^ sz)];
            #pragma unroll
            for (int j = 0; j < 4; j++) {
                int n = wn + j * 8 + g;
                unsigned bf[2] = { uV[colb * 64 + (n ^ (8 * cq))],
                                   uV[(colb + 4) * 64 + (n ^ (8 * cq))] };
                mma_tf32(acc_o[j], af, bf);
            }
        }
    }

    __syncthreads();
    // ctx written tf32-rounded: it feeds the (pre-rounded-operand) O GEMM
    float il0 = 1.0f / fL[r0], il1 = 1.0f / fL[r1];
    #pragma unroll
    for (int j = 0; j < 4; j++) {
        int c = wn + j * 8 + 2 * cq;
        float* d0 = ctx + ((size_t)(b * NT + t0 + r0)) * ND + h * HD + c;
        float* d1 = ctx + ((size_t)(b * NT + t0 + r1)) * ND + h * HD + c;
        d0[0] = roundtf(acc_o[j][0] * il0); d0[1] = roundtf(acc_o[j][1] * il0);
        d1[0] = roundtf(acc_o[j][2] * il1); d1[1] = roundtf(acc_o[j][3] * il1);
    }
}

// ---------------------------------------------------------------------------
extern "C" void kernel_launch(void* const* d_in, const int* in_sizes, int n_in,
                              void* d_out, int out_size) {
    const float* x    = (const float*)d_in[0];
    const float* pos  = (const float*)d_in[1];
    const float* ln_g = (const float*)d_in[2];
    const float* ln_b = (const float*)d_in[3];
    const float* Wq   = (const float*)d_in[4];
    const float* bq   = (const float*)d_in[5];
    const float* Wk   = (const float*)d_in[6];
    const float* bk   = (const float*)d_in[7];
    const float* Wv   = (const float*)d_in[8];
    const float* bv   = (const float*)d_in[9];
    const float* Wp   = (const float*)d_in[10];
    const float* bp   = (const float*)d_in[11];
    const float* cb   = (const float*)d_in[12];
    const float* pb   = (const float*)d_in[13];
    const float* Wo   = (const float*)d_in[14];
    const float* bo   = (const float*)d_in[15];
    float* out = (float*)d_out;

    float *xn, *q, *k, *v, *p, *ctx, *wr, *posr;
    cudaGetSymbolAddress((void**)&xn,   g_xn);
    cudaGetSymbolAddress((void**)&q,    g_q);
    cudaGetSymbolAddress((void**)&k,    g_kk);
    cudaGetSymbolAddress((void**)&v,    g_v);
    cudaGetSymbolAddress((void**)&p,    g_pp);
    cudaGetSymbolAddress((void**)&ctx,  g_ctx);
    cudaGetSymbolAddress((void**)&wr,   g_wr);
    cudaGetSymbolAddress((void**)&posr, g_posr);

    cudaFuncSetAttribute(flash_attn, cudaFuncAttributeMaxDynamicSharedMemorySize,
                         FLASH_SMEM);
    cudaFuncSetAttribute(proj_batched, cudaFuncAttributeMaxDynamicSharedMemorySize,
                         64 * 1024);
    cudaFuncSetAttribute(gemm_out, cudaFuncAttributeMaxDynamicSharedMemorySize,
                         64 * 1024);

    const int WN = ND * ND;   // 262144

    // 0. Pre-round weights + pos_emb
    RoundSet rs;
    rs.src[0] = Wq;  rs.dst[0] = wr + 0 * WN; rs.n4[0] = WN / 4;
    rs.src[1] = Wk;  rs.dst[1] = wr + 1 * WN; rs.n4[1] = WN / 4;
    rs.src[2] = Wv;  rs.dst[2] = wr + 2 * WN; rs.n4[2] = WN / 4;
    rs.src[3] = Wp;  rs.dst[3] = wr + 3 * WN; rs.n4[3] = WN / 4;
    rs.src[4] = Wo;  rs.dst[4] = wr + 4 * WN; rs.n4[4] = WN / 4;
    rs.src[5] = pos; rs.dst[5] = posr;        rs.n4[5] = (NB * NP * ND) / 4;
    round_copy<<<dim3(512, 6), 256>>>(rs);

    // 1. LayerNorm (rounded output)
    ln_kernel<<<NB * NT, 256>>>(x, ln_g, ln_b, xn);

    // 2. Q/K/V/P projections, batched in one launch
    ProjSet ps;
    ps.A[0] = xn;   ps.W[0] = wr + 0 * WN; ps.bias[0] = bq; ps.C[0] = q; ps.M[0] = NB * NT;
    ps.A[1] = xn;   ps.W[1] = wr + 1 * WN; ps.bias[1] = bk; ps.C[1] = k; ps.M[1] = NB * NT;
    ps.A[2] = xn;   ps.W[2] = wr + 2 * WN; ps.bias[2] = bv; ps.C[2] = v; ps.M[2] = NB * NT;
    ps.A[3] = posr; ps.W[3] = wr + 3 * WN; ps.bias[3] = bp; ps.C[3] = p; ps.M[3] = NB * NP;
    proj_batched<<<dim3(4, 128, 4), 256, 64 * 1024>>>(ps);

    // 3. Fused attention
    dim3 ga(NT / 64, NB * NH);
    flash_attn<<<ga, 256, FLASH_SMEM>>>(q, k, v, p, cb, pb, ctx);

    // 4. Output projection -> d_out (unrounded)
    gemm_out<<<dim3(4, 64), 256, 64 * 1024>>>(ctx, wr + 4 * WN, bo, out, NB * NT);
}

// round 13
// speedup vs baseline: 3.8455x; 1.1654x over previous
#include <cuda_runtime.h>

// ---------------------------------------------------------------------------
// Transformer-XL relative multi-head attention, TF32 tensor cores, fused
// flash attention with cp.async double-buffered K/V/band prefetch.
// B=16, T=512, D=512, H=8, hd=64, P=2T-1=1023.
// ---------------------------------------------------------------------------

#define NB 16
#define NT 512
#define ND 512
#define NH 8
#define HD 64
#define NP (2*NT - 1)   // 1023

__device__ float g_xn  [NB*NT*ND];
__device__ float g_q   [NB*NT*ND];
__device__ float g_kk  [NB*NT*ND];
__device__ float g_v   [NB*NT*ND];
__device__ float g_pp  [NB*NP*ND];
__device__ float g_ctx [NB*NT*ND];
__device__ float g_wr  [5 * ND * ND];       // rounded Wq,Wk,Wv,Wp,Wo
__device__ float g_posr[NB*NP*ND];          // rounded pos_emb

// ---------------------------------------------------------------------------
__device__ __forceinline__ unsigned f2tf32(float x) {
    unsigned u;
    asm("cvt.rna.tf32.f32 %0, %1;" : "=r"(u) : "f"(x));
    return u;
}
__device__ __forceinline__ float roundtf(float x) { return __uint_as_float(f2tf32(x)); }

__device__ __forceinline__ void mma_tf32(float* d, const unsigned* a, const unsigned* b) {
    asm volatile(
        "mma.sync.aligned.m16n8k8.row.col.f32.tf32.tf32.f32 "
        "{%0,%1,%2,%3}, {%4,%5,%6,%7}, {%8,%9}, {%0,%1,%2,%3};"
        : "+f"(d[0]), "+f"(d[1]), "+f"(d[2]), "+f"(d[3])
        : "r"(a[0]), "r"(a[1]), "r"(a[2]), "r"(a[3]), "r"(b[0]), "r"(b[1]));
}

__device__ __forceinline__ unsigned smaddr(const void* p) {
    return (unsigned)__cvta_generic_to_shared(p);
}
#define CP16(dst, src, pred) \
    asm volatile("cp.async.cg.shared.global [%0], [%1], 16, %2;" \
                 :: "r"(dst), "l"(src), "r"((pred) ? 16 : 0))
#define CP_COMMIT() asm volatile("cp.async.commit_group;")
#define CP_WAIT2()  asm volatile("cp.async.wait_group 2;")
#define CP_WAIT0()  asm volatile("cp.async.wait_group 0;")

// ---------------------------------------------------------------------------
// Prep: round weights + pos_emb to tf32-representable f32
// ---------------------------------------------------------------------------
struct RoundSet { const float* src[6]; float* dst[6]; int n4[6]; };

__global__ void round_copy(RoundSet rs) {
    int z = blockIdx.y;
    int n4 = rs.n4[z];
    const float4* s = (const float4*)rs.src[z];
    float4* d = (float4*)rs.dst[z];
    for (int i = blockIdx.x * blockDim.x + threadIdx.x; i < n4;
         i += gridDim.x * blockDim.x) {
        float4 v = s[i];
        d[i] = make_float4(roundtf(v.x), roundtf(v.y), roundtf(v.z), roundtf(v.w));
    }
}

// ---------------------------------------------------------------------------
// LayerNorm (writes tf32-rounded output)
// ---------------------------------------------------------------------------
__global__ void ln_kernel(const float* __restrict__ x,
                          const float* __restrict__ gam,
                          const float* __restrict__ bet,
                          float* __restrict__ xn) {
    int row = blockIdx.x;
    int tid = threadIdx.x;
    const float* xr = x + (size_t)row * ND;
    float v0 = xr[tid], v1 = xr[tid + 256];
    float s = v0 + v1, ss = v0*v0 + v1*v1;
    #pragma unroll
    for (int o = 16; o > 0; o >>= 1) {
        s  += __shfl_down_sync(0xffffffffu, s,  o);
        ss += __shfl_down_sync(0xffffffffu, ss, o);
    }
    __shared__ float sh[16];
    __shared__ float smu, srs;
    int wid = tid >> 5, lane = tid & 31;
    if (lane == 0) { sh[wid] = s; sh[wid + 8] = ss; }
    __syncthreads();
    if (tid == 0) {
        float t1 = 0.f, t2 = 0.f;
        #pragma unroll
        for (int i = 0; i < 8; i++) { t1 += sh[i]; t2 += sh[i + 8]; }
        float mu  = t1 * (1.0f / ND);
        float var = t2 * (1.0f / ND) - mu * mu;
        smu = mu;
        srs = rsqrtf(var + 1e-5f);
    }
    __syncthreads();
    float mu = smu, rs = srs;
    float* xo = xn + (size_t)row * ND;
    xo[tid]       = roundtf((v0 - mu) * rs * gam[tid]       + bet[tid]);
    xo[tid + 256] = roundtf((v1 - mu) * rs * gam[tid + 256] + bet[tid + 256]);
}

// ---------------------------------------------------------------------------
// TF32 GEMM core (unchanged): C[M,512] = A[M,512] @ W[512,512]^T + bias
// ---------------------------------------------------------------------------
template<bool ROUND>
__device__ __forceinline__ void gemm_core(const float* __restrict__ A,
                                          const float* __restrict__ W,
                                          const float* __restrict__ bias,
                                          float* __restrict__ C, int M,
                                          int m0, int n0,
                                          unsigned* sA, unsigned* sB) {
    const int tid = threadIdx.x, lane = tid & 31, wid = tid >> 5;
    const int g = lane >> 2, cq = lane & 3;
    const int wm = (wid >> 2) * 64, wn = (wid & 3) * 32;
    const int sza = 4 * ((g >> 1) & 3);

    const int r  = tid >> 2;
    const int cc = (tid & 3) * 4;
    const int sc = cc ^ (4 * ((r >> 1) & 3));
    const int e0 = r * 16 + sc, e1 = (r + 64) * 16 + sc;
    const unsigned aB = smaddr(sA), bB = smaddr(sB);

    const int ar0 = m0 + r, ar1 = m0 + r + 64;
    const float* a0 = A + (size_t)(ar0 < M ? ar0 : 0) * 512 + cc;
    const float* a1 = A + (size_t)(ar1 < M ? ar1 : 0) * 512 + cc;
    const float* w0 = W + (size_t)(n0 + r) * 512 + cc;
    const float* w1 = W + (size_t)(n0 + r + 64) * 512 + cc;
    const bool p0 = ar0 < M, p1 = ar1 < M;

    float acc[16][4];
    #pragma unroll
    for (int i = 0; i < 16; i++)
        #pragma unroll
        for (int j = 0; j < 4; j++) acc[i][j] = 0.f;

    auto issue = [&](int stage, int kc) {
        unsigned ab = aB + stage * 8192, bb = bB + stage * 8192;
        int ko = kc * 16;
        CP16(ab + e0 * 4, a0 + ko, p0);
        CP16(ab + e1 * 4, a1 + ko, p1);
        CP16(bb + e0 * 4, w0 + ko, true);
        CP16(bb + e1 * 4, w1 + ko, true);
    };
    auto compute = [&](int stage) {
        const unsigned* As = sA + stage * 2048;
        const unsigned* Bs = sB + stage * 2048;
        #pragma unroll
        for (int ks = 0; ks < 2; ks++) {
            int colb = ks * 8 + cq;
            unsigned af[4][4], bf[4][2];
            #pragma unroll
            for (int i = 0; i < 4; i++) {
                int rr = wm + i * 16 + g;
                af[i][0] = As[rr * 16 + (colb ^ sza)];
                af[i][1] = As[(rr + 8) * 16 + (colb ^ sza)];
                af[i][2] = As[rr * 16 + ((colb + 4) ^ sza)];
                af[i][3] = As[(rr + 8) * 16 + ((colb + 4) ^ sza)];
            }
            #pragma unroll
            for (int j = 0; j < 4; j++) {
                int rr = wn + j * 8 + g;
                bf[j][0] = Bs[rr * 16 + (colb ^ sza)];
                bf[j][1] = Bs[rr * 16 + ((colb + 4) ^ sza)];
            }
            #pragma unroll
            for (int i = 0; i < 4; i++)
                #pragma unroll
                for (int j = 0; j < 4; j++)
                    mma_tf32(acc[i * 4 + j], af[i], bf[j]);
        }
    };

    issue(0, 0); CP_COMMIT();
    issue(1, 1); CP_COMMIT();
    issue(2, 2); CP_COMMIT();
    for (int kc = 0; kc < 32; kc++) {
        CP_WAIT2();
        __syncthreads();
        if (kc + 3 < 32) issue((kc + 3) & 3, kc + 3);
        CP_COMMIT();
        compute(kc & 3);
    }

    #pragma unroll
    for (int i = 0; i < 4; i++) {
        int row = m0 + wm + i * 16 + g;
        #pragma unroll
        for (int j = 0; j < 4; j++) {
            int col = n0 + wn + j * 8 + 2 * cq;
            float b0 = __ldg(&bias[col]), b1 = __ldg(&bias[col + 1]);
            float* v = acc[i * 4 + j];
            if (row < M) {
                float o0 = v[0] + b0, o1 = v[1] + b1;
                C[(size_t)row * 512 + col]     = ROUND ? roundtf(o0) : o0;
                C[(size_t)row * 512 + col + 1] = ROUND ? roundtf(o1) : o1;
            }
            if (row + 8 < M) {
                float o0 = v[2] + b0, o1 = v[3] + b1;
                C[(size_t)(row + 8) * 512 + col]     = ROUND ? roundtf(o0) : o0;
                C[(size_t)(row + 8) * 512 + col + 1] = ROUND ? roundtf(o1) : o1;
            }
        }
    }
}

struct ProjSet {
    const float* A[4]; const float* W[4]; const float* bias[4];
    float* C[4]; int M[4];
};

__global__ __launch_bounds__(256, 2) void proj_batched(ProjSet ps) {
    extern __shared__ unsigned gsm[];
    int z = blockIdx.z;
    int M = ps.M[z];
    int m0 = blockIdx.y * 128;
    if (m0 >= M) return;
    gemm_core<true>(ps.A[z], ps.W[z], ps.bias[z], ps.C[z], M,
                    m0, blockIdx.x * 128, gsm, gsm + 4 * 2048);
}

__global__ __launch_bounds__(256, 2) void gemm_out(const float* __restrict__ A,
                                                   const float* __restrict__ W,
                                                   const float* __restrict__ bias,
                                                   float* __restrict__ C, int M) {
    extern __shared__ unsigned gsm[];
    gemm_core<false>(A, W, bias, C, M, blockIdx.y * 128, blockIdx.x * 128,
                     gsm, gsm + 4 * 2048);
}

// ---------------------------------------------------------------------------
// Fused flash attention, cp.async double-buffered K/V/band.
// rel_shift: band rows [448+j0-t0 .. +126], gather index 63 + j - t.
// Row softmax state (m, l) kept in replicated registers; 4 syncs per jt.
// ---------------------------------------------------------------------------
#define PS_STRIDE 136
// uQc 4096 + uQp 4096 + uK 2*4096 + uV 2*4096 + uP 4096 + uB 2*8192 (unsigned)
// + fPS 64*136 + fRed 128 (float)
#define FLASH_SMEM ((4096*3 + 8192*2 + 16384) * 4 + 64*PS_STRIDE*4 + 128*4)

__global__ __launch_bounds__(256) void flash_attn(
    const float* __restrict__ Q, const float* __restrict__ K,
    const float* __restrict__ V, const float* __restrict__ P,
    const float* __restrict__ cb, const float* __restrict__ pb,
    float* __restrict__ ctx) {
    extern __shared__ char smraw[];
    unsigned* uQc = (unsigned*)smraw;     // 64x64
    unsigned* uQp = uQc + 4096;           // 64x64
    unsigned* uK  = uQp + 4096;           // 2 x 64x64
    unsigned* uV  = uK  + 8192;           // 2 x 64x64
    unsigned* uP  = uV  + 8192;           // 64x64
    unsigned* uB  = uP  + 4096;           // 2 x 128x64
    float* fPS  = (float*)(uB + 16384);   // 64 x PS_STRIDE
    float* fRed = fPS + 64 * PS_STRIDE;   // [2][64]

    const int tid = threadIdx.x, lane = tid & 31, wid = tid >> 5;
    const int g = lane >> 2, cq = lane & 3;
    const int wm = (wid >> 1) * 16, wn = (wid & 1) * 32;
    const int t0 = blockIdx.x * 64;
    const int z = blockIdx.y, b = z >> 3, h = z & 7;
    const int sz = 4 * g;

    const float* Qb = Q + (size_t)b * NT * ND + h * HD;
    const float* Kb = K + (size_t)b * NT * ND + h * HD;
    const float* Vb = V + (size_t)b * NT * ND + h * HD;
    const float* Pb = P + (size_t)b * NP * ND + h * HD;

    // ---- prefetch issue for tile t (K, V, band) into buffer t&1 ----
    auto issue_tile = [&](int t) {
        int buf = t & 1;
        int jj0 = t * 64;
        int pb0 = 448 + jj0 - t0;
        unsigned kB = smaddr(uK + buf * 4096);
        unsigned vB = smaddr(uV + buf * 4096);
        unsigned bB = smaddr(uB + buf * 8192);
        #pragma unroll
        for (int i = 0; i < 4; i++) {
            int idx = tid + i * 256;
            int r = idx >> 4, c4 = (idx & 15) * 4;
            CP16(kB + (r * 64 + (c4 ^ (4 * (r & 7)))) * 4,
                 Kb + (size_t)(jj0 + r) * ND + c4, true);
            CP16(vB + (r * 64 + (c4 ^ (8 * (r & 3)))) * 4,
                 Vb + (size_t)(jj0 + r) * ND + c4, true);
        }
        #pragma unroll
        for (int i = 0; i < 8; i++) {
            int idx = tid + i * 256;
            int r = idx >> 4, c4 = (idx & 15) * 4;
            // r == 127: cp.async src-size 0 zero-fills the 16 bytes
            CP16(bB + (r * 64 + (c4 ^ (4 * (r & 7)))) * 4,
                 Pb + (size_t)(pb0 + r) * ND + c4, r < 127);
        }
    };

    issue_tile(0);
    CP_COMMIT();

    // ---- Q tile once: qc = q+cb, qp = q+pb ----
    #pragma unroll
    for (int i = 0; i < 4; i++) {
        int idx = tid + i * 256;
        int r = idx >> 4, c4 = (idx & 15) * 4;
        float4 qv  = *reinterpret_cast<const float4*>(Qb + (size_t)(t0 + r) * ND + c4);
        float4 cbv = *reinterpret_cast<const float4*>(cb + h * HD + c4);
        float4 pbv = *reinterpret_cast<const float4*>(pb + h * HD + c4);
        int sc = c4 ^ (4 * (r & 7));
        *reinterpret_cast<uint4*>(&uQc[r * 64 + sc]) =
            make_uint4(f2tf32(qv.x + cbv.x), f2tf32(qv.y + cbv.y),
                       f2tf32(qv.z + cbv.z), f2tf32(qv.w + cbv.w));
        *reinterpret_cast<uint4*>(&uQp[r * 64 + sc]) =
            make_uint4(f2tf32(qv.x + pbv.x), f2tf32(qv.y + pbv.y),
                       f2tf32(qv.z + pbv.z), f2tf32(qv.w + pbv.w));
    }

    // per-thread replicated row state for rows r0 = wm+g, r1 = wm+8+g
    float m0r = -1e30f, m1r = -1e30f, l0r = 0.f, l1r = 0.f;

    float acc_o[4][4];
    #pragma unroll
    for (int j = 0; j < 4; j++)
        #pragma unroll
        for (int q4 = 0; q4 < 4; q4++) acc_o[j][q4] = 0.f;

    const int r0 = wm + g, r1 = wm + 8 + g;

    for (int jt = 0; jt < 8; jt++) {
        const int buf = jt & 1;
        const unsigned* bK = uK + buf * 4096;
        const unsigned* bV = uV + buf * 4096;
        const unsigned* bB = uB + buf * 8192;

        CP_WAIT0();
        __syncthreads();                 // sync A: tile ready, prev buffers free
        if (jt < 7) { issue_tile(jt + 1); CP_COMMIT(); }

        // ---- content MMA: qc @ k^T ----
        float acc_c[4][4];
        #pragma unroll
        for (int j = 0; j < 4; j++)
            #pragma unroll
            for (int q4 = 0; q4 < 4; q4++) acc_c[j][q4] = 0.f;
        #pragma unroll
        for (int ks = 0; ks < 8; ks++) {
            int colb = ks * 8 + cq;
            unsigned af[4];
            af[0] = uQc[r0 * 64 + (colb ^ sz)];
            af[1] = uQc[r1 * 64 + (colb ^ sz)];
            af[2] = uQc[r0 * 64 + ((colb + 4) ^ sz)];
            af[3] = uQc[r1 * 64 + ((colb + 4) ^ sz)];
            #pragma unroll
            for (int j = 0; j < 4; j++) {
                int n = wn + j * 8 + g;
                unsigned bf[2] = { bK[n * 64 + (colb ^ sz)],
                                   bK[n * 64 + ((colb + 4) ^ sz)] };
                mma_tf32(acc_c[j], af, bf);
            }
        }

        // ---- band MMA: qp @ band^T, 2 passes of n=64, result -> fPS ----
        #pragma unroll
        for (int pass = 0; pass < 2; pass++) {
            float acc_p[4][4];
            #pragma unroll
            for (int j = 0; j < 4; j++)
                #pragma unroll
                for (int q4 = 0; q4 < 4; q4++) acc_p[j][q4] = 0.f;
            #pragma unroll
            for (int ks = 0; ks < 8; ks++) {
                int colb = ks * 8 + cq;
                unsigned af[4];
                af[0] = uQp[r0 * 64 + (colb ^ sz)];
                af[1] = uQp[r1 * 64 + (colb ^ sz)];
                af[2] = uQp[r0 * 64 + ((colb + 4) ^ sz)];
                af[3] = uQp[r1 * 64 + ((colb + 4) ^ sz)];
                #pragma unroll
                for (int j = 0; j < 4; j++) {
                    int n = pass * 64 + wn + j * 8 + g;
                    unsigned bf[2] = { bB[n * 64 + (colb ^ sz)],
                                       bB[n * 64 + ((colb + 4) ^ sz)] };
                    mma_tf32(acc_p[j], af, bf);
                }
            }
            #pragma unroll
            for (int j = 0; j < 4; j++) {
                int c = pass * 64 + wn + j * 8 + 2 * cq;
                fPS[r0 * PS_STRIDE + c]     = acc_p[j][0];
                fPS[r0 * PS_STRIDE + c + 1] = acc_p[j][1];
                fPS[r1 * PS_STRIDE + c]     = acc_p[j][2];
                fPS[r1 * PS_STRIDE + c + 1] = acc_p[j][3];
            }
        }
        __syncthreads();                 // sync B: fPS visible

        // ---- gather diagonal, combine, row maxima ----
        float s[4][4];
        float rmax0 = -1e30f, rmax1 = -1e30f;
        #pragma unroll
        for (int j = 0; j < 4; j++) {
            int c = wn + j * 8 + 2 * cq;
            s[j][0] = (acc_c[j][0] + fPS[r0 * PS_STRIDE + (63 + c     - r0)]) * 0.125f;
            s[j][1] = (acc_c[j][1] + fPS[r0 * PS_STRIDE + (63 + c + 1 - r0)]) * 0.125f;
            s[j][2] = (acc_c[j][2] + fPS[r1 * PS_STRIDE + (63 + c     - r1)]) * 0.125f;
            s[j][3] = (acc_c[j][3] + fPS[r1 * PS_STRIDE + (63 + c + 1 - r1)]) * 0.125f;
            rmax0 = fmaxf(rmax0, fmaxf(s[j][0], s[j][1]));
            rmax1 = fmaxf(rmax1, fmaxf(s[j][2], s[j][3]));
        }
        rmax0 = fmaxf(rmax0, __shfl_xor_sync(0xffffffffu, rmax0, 1));
        rmax0 = fmaxf(rmax0, __shfl_xor_sync(0xffffffffu, rmax0, 2));
        rmax1 = fmaxf(rmax1, __shfl_xor_sync(0xffffffffu, rmax1, 1));
        rmax1 = fmaxf(rmax1, __shfl_xor_sync(0xffffffffu, rmax1, 2));
        if (cq == 0) {
            fRed[(wid & 1) * 64 + r0] = rmax0;
            fRed[(wid & 1) * 64 + r1] = rmax1;
        }
        __syncthreads();                 // sync C: maxima visible

        // ---- new max / alpha in registers (replicated per row) ----
        float mn0 = fmaxf(m0r, fmaxf(fRed[r0], fRed[64 + r0]));
        float mn1 = fmaxf(m1r, fmaxf(fRed[r1], fRed[64 + r1]));
        float al0 = __expf(m0r - mn0), al1 = __expf(m1r - mn1);
        m0r = mn0; m1r = mn1;

        // ---- exp, store P (tf32), rescale O, row sums ----
        float rsum0 = 0.f, rsum1 = 0.f;
        #pragma unroll
        for (int j = 0; j < 4; j++) {
            float p00 = __expf(s[j][0] - mn0), p01 = __expf(s[j][1] - mn0);
            float p10 = __expf(s[j][2] - mn1), p11 = __expf(s[j][3] - mn1);
            rsum0 += p00 + p01;
            rsum1 += p10 + p11;
            int c = wn + j * 8 + 2 * cq;
            uP[r0 * 64 + ( c      ^ sz)] = f2tf32(p00);
            uP[r0 * 64 + ((c + 1) ^ sz)] = f2tf32(p01);
            uP[r1 * 64 + ( c      ^ sz)] = f2tf32(p10);
            uP[r1 * 64 + ((c + 1) ^ sz)] = f2tf32(p11);
            acc_o[j][0] *= al0; acc_o[j][1] *= al0;
            acc_o[j][2] *= al1; acc_o[j][3] *= al1;
        }
        rsum0 += __shfl_xor_sync(0xffffffffu, rsum0, 1);
        rsum0 += __shfl_xor_sync(0xffffffffu, rsum0, 2);
        rsum1 += __shfl_xor_sync(0xffffffffu, rsum1, 1);
        rsum1 += __shfl_xor_sync(0xffffffffu, rsum1, 2);
        if (cq == 0) {
            fRed[(wid & 1) * 64 + r0] = rsum0;
            fRed[(wid & 1) * 64 + r1] = rsum1;
        }
        __syncthreads();                 // sync D: sums + uP visible

        l0r = l0r * al0 + fRed[r0] + fRed[64 + r0];
        l1r = l1r * al1 + fRed[r1] + fRed[64 + r1];

        // ---- O += P @ V ----
        #pragma unroll
        for (int ks = 0; ks < 8; ks++) {
            int colb = ks * 8 + cq;
            unsigned af[4];
            af[0] = uP[r0 * 64 + (colb ^ sz)];
            af[1] = uP[r1 * 64 + (colb ^ sz)];
            af[2] = uP[r0 * 64 + ((colb + 4) ^ sz)];
            af[3] = uP[r1 * 64 + ((colb + 4) ^ sz)];
            #pragma unroll
            for (int j = 0; j < 4; j++) {
                int n = wn + j * 8 + g;
                unsigned bf[2] = { bV[colb * 64 + (n ^ (8 * cq))],
                                   bV[(colb + 4) * 64 + (n ^ (8 * cq))] };
                mma_tf32(acc_o[j], af, bf);
            }
        }
    }

    // ---- epilogue: all state in registers ----
    float il0 = 1.0f / l0r, il1 = 1.0f / l1r;
    #pragma unroll
    for (int j = 0; j < 4; j++) {
        int c = wn + j * 8 + 2 * cq;
        float* d0 = ctx + ((size_t)(b * NT + t0 + r0)) * ND + h * HD + c;
        float* d1 = ctx + ((size_t)(b * NT + t0 + r1)) * ND + h * HD + c;
        d0[0] = roundtf(acc_o[j][0] * il0); d0[1] = roundtf(acc_o[j][1] * il0);
        d1[0] = roundtf(acc_o[j][2] * il1); d1[1] = roundtf(acc_o[j][3] * il1);
    }
}

// ---------------------------------------------------------------------------
extern "C" void kernel_launch(void* const* d_in, const int* in_sizes, int n_in,
                              void* d_out, int out_size) {
    const float* x    = (const float*)d_in[0];
    const float* pos  = (const float*)d_in[1];
    const float* ln_g = (const float*)d_in[2];
    const float* ln_b = (const float*)d_in[3];
    const float* Wq   = (const float*)d_in[4];
    const float* bq   = (const float*)d_in[5];
    const float* Wk   = (const float*)d_in[6];
    const float* bk   = (const float*)d_in[7];
    const float* Wv   = (const float*)d_in[8];
    const float* bv   = (const float*)d_in[9];
    const float* Wp   = (const float*)d_in[10];
    const float* bp   = (const float*)d_in[11];
    const float* cb   = (const float*)d_in[12];
    const float* pb   = (const float*)d_in[13];
    const float* Wo   = (const float*)d_in[14];
    const float* bo   = (const float*)d_in[15];
    float* out = (float*)d_out;

    float *xn, *q, *k, *v, *p, *ctx, *wr, *posr;
    cudaGetSymbolAddress((void**)&xn,   g_xn);
    cudaGetSymbolAddress((void**)&q,    g_q);
    cudaGetSymbolAddress((void**)&k,    g_kk);
    cudaGetSymbolAddress((void**)&v,    g_v);
    cudaGetSymbolAddress((void**)&p,    g_pp);
    cudaGetSymbolAddress((void**)&ctx,  g_ctx);
    cudaGetSymbolAddress((void**)&wr,   g_wr);
    cudaGetSymbolAddress((void**)&posr, g_posr);

    cudaFuncSetAttribute(flash_attn, cudaFuncAttributeMaxDynamicSharedMemorySize,
                         FLASH_SMEM);
    cudaFuncSetAttribute(proj_batched, cudaFuncAttributeMaxDynamicSharedMemorySize,
                         64 * 1024);
    cudaFuncSetAttribute(gemm_out, cudaFuncAttributeMaxDynamicSharedMemorySize,
                         64 * 1024);

    const int WN = ND * ND;   // 262144

    // 0. Pre-round weights + pos_emb
    RoundSet rs;
    rs.src[0] = Wq;  rs.dst[0] = wr + 0 * WN; rs.n4[0] = WN / 4;
    rs.src[1] = Wk;  rs.dst[1] = wr + 1 * WN; rs.n4[1] = WN / 4;
    rs.src[2] = Wv;  rs.dst[2] = wr + 2 * WN; rs.n4[2] = WN / 4;
    rs.src[3] = Wp;  rs.dst[3] = wr + 3 * WN; rs.n4[3] = WN / 4;
    rs.src[4] = Wo;  rs.dst[4] = wr + 4 * WN; rs.n4[4] = WN / 4;
    rs.src[5] = pos; rs.dst[5] = posr;        rs.n4[5] = (NB * NP * ND) / 4;
    round_copy<<<dim3(512, 6), 256>>>(rs);

    // 1. LayerNorm (rounded output)
    ln_kernel<<<NB * NT, 256>>>(x, ln_g, ln_b, xn);

    // 2. Q/K/V/P projections, batched
    ProjSet ps;
    ps.A[0] = xn;   ps.W[0] = wr + 0 * WN; ps.bias[0] = bq; ps.C[0] = q; ps.M[0] = NB * NT;
    ps.A[1] = xn;   ps.W[1] = wr + 1 * WN; ps.bias[1] = bk; ps.C[1] = k; ps.M[1] = NB * NT;
    ps.A[2] = xn;   ps.W[2] = wr + 2 * WN; ps.bias[2] = bv; ps.C[2] = v; ps.M[2] = NB * NT;
    ps.A[3] = posr; ps.W[3] = wr + 3 * WN; ps.bias[3] = bp; ps.C[3] = p; ps.M[3] = NB * NP;
    proj_batched<<<dim3(4, 128, 4), 256, 64 * 1024>>>(ps);

    // 3. Fused attention (prefetched, 4 syncs/iter)
    dim3 ga(NT / 64, NB * NH);
    flash_attn<<<ga, 256, FLASH_SMEM>>>(q, k, v, p, cb, pb, ctx);

    // 4. Output projection -> d_out
    gemm_out<<<dim3(4, 64), 256, 64 * 1024>>>(ctx, wr + 4 * WN, bo, out, NB * NT);
}

// round 15
// speedup vs baseline: 4.3476x; 1.1306x over previous
#include <cuda_runtime.h>

// ---------------------------------------------------------------------------
// Transformer-XL relative multi-head attention, TF32 tensor cores, fused
// flash attention, cp.async prefetch, ldmatrix fragment loads.
// B=16, T=512, D=512, H=8, hd=64, P=2T-1=1023.
// ---------------------------------------------------------------------------

#define NB 16
#define NT 512
#define ND 512
#define NH 8
#define HD 64
#define NP (2*NT - 1)   // 1023

__device__ float g_xn  [NB*NT*ND];
__device__ float g_q   [NB*NT*ND];
__device__ float g_kk  [NB*NT*ND];
__device__ float g_v   [NB*NT*ND];
__device__ float g_pp  [NB*NP*ND];
__device__ float g_ctx [NB*NT*ND];
__device__ float g_wr  [5 * ND * ND];       // rounded Wq,Wk,Wv,Wp,Wo
__device__ float g_posr[NB*NP*ND];          // rounded pos_emb

// ---------------------------------------------------------------------------
__device__ __forceinline__ unsigned f2tf32(float x) {
    unsigned u;
    asm("cvt.rna.tf32.f32 %0, %1;" : "=r"(u) : "f"(x));
    return u;
}
__device__ __forceinline__ float roundtf(float x) { return __uint_as_float(f2tf32(x)); }

__device__ __forceinline__ void mma_tf32(float* d, const unsigned* a, const unsigned* b) {
    asm volatile(
        "mma.sync.aligned.m16n8k8.row.col.f32.tf32.tf32.f32 "
        "{%0,%1,%2,%3}, {%4,%5,%6,%7}, {%8,%9}, {%0,%1,%2,%3};"
        : "+f"(d[0]), "+f"(d[1]), "+f"(d[2]), "+f"(d[3])
        : "r"(a[0]), "r"(a[1]), "r"(a[2]), "r"(a[3]), "r"(b[0]), "r"(b[1]));
}

// ldmatrix x4: 4 8x8 b16 matrices; lane l addresses matrix l>>3, row l&7.
// In tf32 terms each matrix = 8 rows x 4 tf32 cols; lane gets (l>>2, l&3).
__device__ __forceinline__ void ldsm4(unsigned* d, unsigned addr) {
    asm volatile("ldmatrix.sync.aligned.m8n8.x4.shared.b16 {%0,%1,%2,%3}, [%4];"
                 : "=r"(d[0]), "=r"(d[1]), "=r"(d[2]), "=r"(d[3]) : "r"(addr));
}

__device__ __forceinline__ unsigned smaddr(const void* p) {
    return (unsigned)__cvta_generic_to_shared(p);
}
#define CP16(dst, src, pred) \
    asm volatile("cp.async.cg.shared.global [%0], [%1], 16, %2;" \
                 :: "r"(dst), "l"(src), "r"((pred) ? 16 : 0))
#define CP_COMMIT() asm volatile("cp.async.commit_group;")
#define CP_WAIT2()  asm volatile("cp.async.wait_group 2;")
#define CP_WAIT0()  asm volatile("cp.async.wait_group 0;")

// ---------------------------------------------------------------------------
// Prep: round weights + pos_emb to tf32-representable f32
// ---------------------------------------------------------------------------
struct RoundSet { const float* src[6]; float* dst[6]; int n4[6]; };

__global__ void round_copy(RoundSet rs) {
    int z = blockIdx.y;
    int n4 = rs.n4[z];
    const float4* s = (const float4*)rs.src[z];
    float4* d = (float4*)rs.dst[z];
    for (int i = blockIdx.x * blockDim.x + threadIdx.x; i < n4;
         i += gridDim.x * blockDim.x) {
        float4 v = s[i];
        d[i] = make_float4(roundtf(v.x), roundtf(v.y), roundtf(v.z), roundtf(v.w));
    }
}

// ---------------------------------------------------------------------------
// LayerNorm (writes tf32-rounded output)
// ---------------------------------------------------------------------------
__global__ void ln_kernel(const float* __restrict__ x,
                          const float* __restrict__ gam,
                          const float* __restrict__ bet,
                          float* __restrict__ xn) {
    int row = blockIdx.x;
    int tid = threadIdx.x;
    const float* xr = x + (size_t)row * ND;
    float v0 = xr[tid], v1 = xr[tid + 256];
    float s = v0 + v1, ss = v0*v0 + v1*v1;
    #pragma unroll
    for (int o = 16; o > 0; o >>= 1) {
        s  += __shfl_down_sync(0xffffffffu, s,  o);
        ss += __shfl_down_sync(0xffffffffu, ss, o);
    }
    __shared__ float sh[16];
    __shared__ float smu, srs;
    int wid = tid >> 5, lane = tid & 31;
    if (lane == 0) { sh[wid] = s; sh[wid + 8] = ss; }
    __syncthreads();
    if (tid == 0) {
        float t1 = 0.f, t2 = 0.f;
        #pragma unroll
        for (int i = 0; i < 8; i++) { t1 += sh[i]; t2 += sh[i + 8]; }
        float mu  = t1 * (1.0f / ND);
        float var = t2 * (1.0f / ND) - mu * mu;
        smu = mu;
        srs = rsqrtf(var + 1e-5f);
    }
    __syncthreads();
    float mu = smu, rs = srs;
    float* xo = xn + (size_t)row * ND;
    xo[tid]       = roundtf((v0 - mu) * rs * gam[tid]       + bet[tid]);
    xo[tid + 256] = roundtf((v1 - mu) * rs * gam[tid + 256] + bet[tid + 256]);
}

// ---------------------------------------------------------------------------
// TF32 GEMM core: C[M,512] = A[M,512] @ W[512,512]^T + bias.
// 128x128 tile, BK=16, 4-stage cp.async, ldmatrix fragment loads.
// Smem swizzle: sc = cc ^ (4*((r>>1)&3)); frag rows offset by multiples of 8
// so the swizzle term is lane-constant for ldmatrix addressing.
// ---------------------------------------------------------------------------
template<bool ROUND>
__device__ __forceinline__ void gemm_core(const float* __restrict__ A,
                                          const float* __restrict__ W,
                                          const float* __restrict__ bias,
                                          float* __restrict__ C, int M,
                                          int m0, int n0,
                                          unsigned* sA, unsigned* sB) {
    const int tid = threadIdx.x, lane = tid & 31, wid = tid >> 5;
    const int g = lane >> 2, cq = lane & 3;
    const int wm = (wid >> 2) * 64, wn = (wid & 3) * 32;

    // ldmatrix geometry
    const int lane7 = lane & 7;
    const int mhi   = lane >> 3;
    const int swg4  = 4 * ((lane7 >> 1) & 3);
    const int rowAg = wm + ((mhi & 1) << 3) + lane7;
    const unsigned coA4 = (unsigned)(((((mhi >> 1) << 2)) ^ swg4) << 2);
    const int rowBg = wn + ((mhi >> 1) << 3) + lane7;
    const unsigned coB4 = (unsigned)(((((mhi & 1) << 2)) ^ swg4) << 2);
    const unsigned aFragB = smaddr(sA) + rowAg * 64;
    const unsigned bFragB = smaddr(sB) + rowBg * 64;

    // copy geometry
    const int r  = tid >> 2;
    const int cc = (tid & 3) * 4;
    const int sc = cc ^ (4 * ((r >> 1) & 3));
    const int e0 = r * 16 + sc, e1 = (r + 64) * 16 + sc;
    const unsigned aB = smaddr(sA), bB = smaddr(sB);

    const int ar0 = m0 + r, ar1 = m0 + r + 64;
    const float* a0 = A + (size_t)(ar0 < M ? ar0 : 0) * 512 + cc;
    const float* a1 = A + (size_t)(ar1 < M ? ar1 : 0) * 512 + cc;
    const float* w0 = W + (size_t)(n0 + r) * 512 + cc;
    const float* w1 = W + (size_t)(n0 + r + 64) * 512 + cc;
    const bool p0 = ar0 < M, p1 = ar1 < M;

    float acc[16][4];
    #pragma unroll
    for (int i = 0; i < 16; i++)
        #pragma unroll
        for (int j = 0; j < 4; j++) acc[i][j] = 0.f;

    auto issue = [&](int stage, int kc) {
        unsigned ab = aB + stage * 8192, bb = bB + stage * 8192;
        int ko = kc * 16;
        CP16(ab + e0 * 4, a0 + ko, p0);
        CP16(ab + e1 * 4, a1 + ko, p1);
        CP16(bb + e0 * 4, w0 + ko, true);
        CP16(bb + e1 * 4, w1 + ko, true);
    };
    auto compute = [&](int stage) {
        const unsigned aSt = aFragB + stage * 8192;
        const unsigned bSt = bFragB + stage * 8192;
        #pragma unroll
        for (int ks = 0; ks < 2; ks++) {
            unsigned kx = ks * 32;
            unsigned af[4][4], b0[4], b1[4];
            #pragma unroll
            for (int i = 0; i < 4; i++)
                ldsm4(af[i], aSt + i * 1024 + (kx ^ coA4));
            ldsm4(b0, bSt + (kx ^ coB4));
            ldsm4(b1, bSt + 1024 + (kx ^ coB4));
            #pragma unroll
            for (int i = 0; i < 4; i++) {
                mma_tf32(acc[i * 4 + 0], af[i], b0);
                mma_tf32(acc[i * 4 + 1], af[i], b0 + 2);
                mma_tf32(acc[i * 4 + 2], af[i], b1);
                mma_tf32(acc[i * 4 + 3], af[i], b1 + 2);
            }
        }
    };

    issue(0, 0); CP_COMMIT();
    issue(1, 1); CP_COMMIT();
    issue(2, 2); CP_COMMIT();
    for (int kc = 0; kc < 32; kc++) {
        CP_WAIT2();
        __syncthreads();
        if (kc + 3 < 32) issue((kc + 3) & 3, kc + 3);
        CP_COMMIT();
        compute(kc & 3);
    }

    #pragma unroll
    for (int i = 0; i < 4; i++) {
        int row = m0 + wm + i * 16 + g;
        #pragma unroll
        for (int j = 0; j < 4; j++) {
            int col = n0 + wn + j * 8 + 2 * cq;
            float b0 = __ldg(&bias[col]), b1 = __ldg(&bias[col + 1]);
            float* v = acc[i * 4 + j];
            if (row < M) {
                float o0 = v[0] + b0, o1 = v[1] + b1;
                C[(size_t)row * 512 + col]     = ROUND ? roundtf(o0) : o0;
                C[(size_t)row * 512 + col + 1] = ROUND ? roundtf(o1) : o1;
            }
            if (row + 8 < M) {
                float o0 = v[2] + b0, o1 = v[3] + b1;
                C[(size_t)(row + 8) * 512 + col]     = ROUND ? roundtf(o0) : o0;
                C[(size_t)(row + 8) * 512 + col + 1] = ROUND ? roundtf(o1) : o1;
            }
        }
    }
}

struct ProjSet {
    const float* A[4]; const float* W[4]; const float* bias[4];
    float* C[4]; int M[4];
};

__global__ __launch_bounds__(256, 2) void proj_batched(ProjSet ps) {
    extern __shared__ unsigned gsm[];
    int z = blockIdx.z;
    int M = ps.M[z];
    int m0 = blockIdx.y * 128;
    if (m0 >= M) return;
    gemm_core<true>(ps.A[z], ps.W[z], ps.bias[z], ps.C[z], M,
                    m0, blockIdx.x * 128, gsm, gsm + 4 * 2048);
}

__global__ __launch_bounds__(256, 2) void gemm_out(const float* __restrict__ A,
                                                   const float* __restrict__ W,
                                                   const float* __restrict__ bias,
                                                   float* __restrict__ C, int M) {
    extern __shared__ unsigned gsm[];
    gemm_core<false>(A, W, bias, C, M, blockIdx.y * 128, blockIdx.x * 128,
                     gsm, gsm + 4 * 2048);
}

// ---------------------------------------------------------------------------
// Fused flash attention, cp.async double-buffered K/V/band, ldmatrix frags.
// rel_shift: band rows [448+j0-t0 .. +126], gather index 63 + j - t.
// Smem swizzle c ^ (4*(r&7)): frag rows offset by multiples of 8 -> the
// swizzle term 4*(r&7) is lane-constant (= 4*(lane&7)) for ldmatrix.
// ---------------------------------------------------------------------------
#define PS_STRIDE 136
#define FLASH_SMEM ((4096*3 + 8192*2 + 16384) * 4 + 64*PS_STRIDE*4 + 128*4)

__global__ __launch_bounds__(256) void flash_attn(
    const float* __restrict__ Q, const float* __restrict__ K,
    const float* __restrict__ V, const float* __restrict__ P,
    const float* __restrict__ cb, const float* __restrict__ pb,
    float* __restrict__ ctx) {
    extern __shared__ char smraw[];
    unsigned* uQc = (unsigned*)smraw;     // 64x64
    unsigned* uQp = uQc + 4096;           // 64x64
    unsigned* uK  = uQp + 4096;           // 2 x 64x64
    unsigned* uV  = uK  + 8192;           // 2 x 64x64
    unsigned* uP  = uV  + 8192;           // 64x64
    unsigned* uB  = uP  + 4096;           // 2 x 128x64
    float* fPS  = (float*)(uB + 16384);   // 64 x PS_STRIDE
    float* fRed = fPS + 64 * PS_STRIDE;   // [2][64]

    const int tid = threadIdx.x, lane = tid & 31, wid = tid >> 5;
    const int g = lane >> 2, cq = lane & 3;
    const int wm = (wid >> 1) * 16, wn = (wid & 1) * 32;
    const int t0 = blockIdx.x * 64;
    const int z = blockIdx.y, b = z >> 3, h = z & 7;
    const int sz = 4 * g;

    // ldmatrix geometry (row&7 == lane&7 for every accessed frag row)
    const int lane7 = lane & 7;
    const int mhi   = lane >> 3;
    const int swl4  = 4 * lane7;
    const int rowA  = wm + ((mhi & 1) << 3) + lane7;
    const unsigned coA4 = (unsigned)(((((mhi >> 1) << 2)) ^ swl4) << 2);
    const int rowBl = ((mhi >> 1) << 3) + lane7;
    const unsigned coB4 = (unsigned)(((((mhi & 1) << 2)) ^ swl4) << 2);
    const unsigned baseQc = smaddr(uQc) + rowA * 256;
    const unsigned baseQp = smaddr(uQp) + rowA * 256;
    const unsigned basePm = smaddr(uP)  + rowA * 256;
    const unsigned rowKoff = (unsigned)((wn + rowBl) * 256);

    const float* Qb = Q + (size_t)b * NT * ND + h * HD;
    const float* Kb = K + (size_t)b * NT * ND + h * HD;
    const float* Vb = V + (size_t)b * NT * ND + h * HD;
    const float* Pb = P + (size_t)b * NP * ND + h * HD;

    auto issue_tile = [&](int t) {
        int buf = t & 1;
        int jj0 = t * 64;
        int pb0 = 448 + jj0 - t0;
        unsigned kB = smaddr(uK + buf * 4096);
        unsigned vB = smaddr(uV + buf * 4096);
        unsigned bB = smaddr(uB + buf * 8192);
        #pragma unroll
        for (int i = 0; i < 4; i++) {
            int idx = tid + i * 256;
            int r = idx >> 4, c4 = (idx & 15) * 4;
            CP16(kB + (r * 64 + (c4 ^ (4 * (r & 7)))) * 4,
                 Kb + (size_t)(jj0 + r) * ND + c4, true);
            CP16(vB + (r * 64 + (c4 ^ (8 * (r & 3)))) * 4,
                 Vb + (size_t)(jj0 + r) * ND + c4, true);
        }
        #pragma unroll
        for (int i = 0; i < 8; i++) {
            int idx = tid + i * 256;
            int r = idx >> 4, c4 = (idx & 15) * 4;
            CP16(bB + (r * 64 + (c4 ^ (4 * (r & 7)))) * 4,
                 Pb + (size_t)(pb0 + r) * ND + c4, r < 127);
        }
    };

    issue_tile(0);
    CP_COMMIT();

    // ---- Q tile once: qc = q+cb, qp = q+pb ----
    #pragma unroll
    for (int i = 0; i < 4; i++) {
        int idx = tid + i * 256;
        int r = idx >> 4, c4 = (idx & 15) * 4;
        float4 qv  = *reinterpret_cast<const float4*>(Qb + (size_t)(t0 + r) * ND + c4);
        float4 cbv = *reinterpret_cast<const float4*>(cb + h * HD + c4);
        float4 pbv = *reinterpret_cast<const float4*>(pb + h * HD + c4);
        int sc = c4 ^ (4 * (r & 7));
        *reinterpret_cast<uint4*>(&uQc[r * 64 + sc]) =
            make_uint4(f2tf32(qv.x + cbv.x), f2tf32(qv.y + cbv.y),
                       f2tf32(qv.z + cbv.z), f2tf32(qv.w + cbv.w));
        *reinterpret_cast<uint4*>(&uQp[r * 64 + sc]) =
            make_uint4(f2tf32(qv.x + pbv.x), f2tf32(qv.y + pbv.y),
                       f2tf32(qv.z + pbv.z), f2tf32(qv.w + pbv.w));
    }

    float m0r = -1e30f, m1r = -1e30f, l0r = 0.f, l1r = 0.f;

    float acc_o[4][4];
    #pragma unroll
    for (int j = 0; j < 4; j++)
        #pragma unroll
        for (int q4 = 0; q4 < 4; q4++) acc_o[j][q4] = 0.f;

    const int r0 = wm + g, r1 = wm + 8 + g;

    for (int jt = 0; jt < 8; jt++) {
        const int buf = jt & 1;
        const unsigned* bV = uV + buf * 4096;
        const unsigned kFrag = smaddr(uK) + buf * 16384 + rowKoff;
        const unsigned bFrag0 = smaddr(uB) + buf * 32768 + (wn + rowBl) * 256;

        CP_WAIT0();
        __syncthreads();                 // sync A: tile ready, prev buffers free
        if (jt < 7) { issue_tile(jt + 1); CP_COMMIT(); }

        // ---- content MMA: qc @ k^T ----
        float acc_c[4][4];
        #pragma unroll
        for (int j = 0; j < 4; j++)
            #pragma unroll
            for (int q4 = 0; q4 < 4; q4++) acc_c[j][q4] = 0.f;
        #pragma unroll
        for (int ks = 0; ks < 8; ks++) {
            unsigned kx = ks * 32;
            unsigned af[4], b0[4], b1[4];
            ldsm4(af, baseQc + (kx ^ coA4));
            ldsm4(b0, kFrag + (kx ^ coB4));
            ldsm4(b1, kFrag + 4096 + (kx ^ coB4));
            mma_tf32(acc_c[0], af, b0);
            mma_tf32(acc_c[1], af, b0 + 2);
            mma_tf32(acc_c[2], af, b1);
            mma_tf32(acc_c[3], af, b1 + 2);
        }

        // ---- band MMA: qp @ band^T, 2 passes of n=64, result -> fPS ----
        #pragma unroll
        for (int pass = 0; pass < 2; pass++) {
            const unsigned bFrag = bFrag0 + pass * 16384;   // +64 rows
            float acc_p[4][4];
            #pragma unroll
            for (int j = 0; j < 4; j++)
                #pragma unroll
                for (int q4 = 0; q4 < 4; q4++) acc_p[j][q4] = 0.f;
            #pragma unroll
            for (int ks = 0; ks < 8; ks++) {
                unsigned kx = ks * 32;
                unsigned af[4], b0[4], b1[4];
                ldsm4(af, baseQp + (kx ^ coA4));
                ldsm4(b0, bFrag + (kx ^ coB4));
                ldsm4(b1, bFrag + 4096 + (kx ^ coB4));
                mma_tf32(acc_p[0], af, b0);
                mma_tf32(acc_p[1], af, b0 + 2);
                mma_tf32(acc_p[2], af, b1);
                mma_tf32(acc_p[3], af, b1 + 2);
            }
            #pragma unroll
            for (int j = 0; j < 4; j++) {
                int c = pass * 64 + wn + j * 8 + 2 * cq;
                fPS[r0 * PS_STRIDE + c]     = acc_p[j][0];
                fPS[r0 * PS_STRIDE + c + 1] = acc_p[j][1];
                fPS[r1 * PS_STRIDE + c]     = acc_p[j][2];
                fPS[r1 * PS_STRIDE + c + 1] = acc_p[j][3];
            }
        }
        __syncthreads();                 // sync B: fPS visible

        // ---- gather diagonal, combine, row maxima ----
        float s[4][4];
        float rmax0 = -1e30f, rmax1 = -1e30f;
        #pragma unroll
        for (int j = 0; j < 4; j++) {
            int c = wn + j * 8 + 2 * cq;
            s[j][0] = (acc_c[j][0] + fPS[r0 * PS_STRIDE + (63 + c     - r0)]) * 0.125f;
            s[j][1] = (acc_c[j][1] + fPS[r0 * PS_STRIDE + (63 + c + 1 - r0)]) * 0.125f;
            s[j][2] = (acc_c[j][2] + fPS[r1 * PS_STRIDE + (63 + c     - r1)]) * 0.125f;
            s[j][3] = (acc_c[j][3] + fPS[r1 * PS_STRIDE + (63 + c + 1 - r1)]) * 0.125f;
            rmax0 = fmaxf(rmax0, fmaxf(s[j][0], s[j][1]));
            rmax1 = fmaxf(rmax1, fmaxf(s[j][2], s[j][3]));
        }
        rmax0 = fmaxf(rmax0, __shfl_xor_sync(0xffffffffu, rmax0, 1));
        rmax0 = fmaxf(rmax0, __shfl_xor_sync(0xffffffffu, rmax0, 2));
        rmax1 = fmaxf(rmax1, __shfl_xor_sync(0xffffffffu, rmax1, 1));
        rmax1 = fmaxf(rmax1, __shfl_xor_sync(0xffffffffu, rmax1, 2));
        if (cq == 0) {
            fRed[(wid & 1) * 64 + r0] = rmax0;
            fRed[(wid & 1) * 64 + r1] = rmax1;
        }
        __syncthreads();                 // sync C: maxima visible

        float mn0 = fmaxf(m0r, fmaxf(fRed[r0], fRed[64 + r0]));
        float mn1 = fmaxf(m1r, fmaxf(fRed[r1], fRed[64 + r1]));
        float al0 = __expf(m0r - mn0), al1 = __expf(m1r - mn1);
        m0r = mn0; m1r = mn1;

        // ---- exp, store P (tf32), rescale O, row sums ----
        float rsum0 = 0.f, rsum1 = 0.f;
        #pragma unroll
        for (int j = 0; j < 4; j++) {
            float p00 = __expf(s[j][0] - mn0), p01 = __expf(s[j][1] - mn0);
            float p10 = __expf(s[j][2] - mn1), p11 = __expf(s[j][3] - mn1);
            rsum0 += p00 + p01;
            rsum1 += p10 + p11;
            int c = wn + j * 8 + 2 * cq;
            uP[r0 * 64 + ( c      ^ sz)] = f2tf32(p00);
            uP[r0 * 64 + ((c + 1) ^ sz)] = f2tf32(p01);
            uP[r1 * 64 + ( c      ^ sz)] = f2tf32(p10);
            uP[r1 * 64 + ((c + 1) ^ sz)] = f2tf32(p11);
            acc_o[j][0] *= al0; acc_o[j][1] *= al0;
            acc_o[j][2] *= al1; acc_o[j][3] *= al1;
        }
        rsum0 += __shfl_xor_sync(0xffffffffu, rsum0, 1);
        rsum0 += __shfl_xor_sync(0xffffffffu, rsum0, 2);
        rsum1 += __shfl_xor_sync(0xffffffffu, rsum1, 1);
        rsum1 += __shfl_xor_sync(0xffffffffu, rsum1, 2);
        if (cq == 0) {
            fRed[(wid & 1) * 64 + r0] = rsum0;
            fRed[(wid & 1) * 64 + r1] = rsum1;
        }
        __syncthreads();                 // sync D: sums + uP visible

        l0r = l0r * al0 + fRed[r0] + fRed[64 + r0];
        l1r = l1r * al1 + fRed[r1] + fRed[64 + r1];

        // ---- O += P @ V ----  (A via ldmatrix, V scalar: layout mismatch)
        #pragma unroll
        for (int ks = 0; ks < 8; ks++) {
            unsigned kx = ks * 32;
            int colb = ks * 8 + cq;
            unsigned af[4];
            ldsm4(af, basePm + (kx ^ coA4));
            #pragma unroll
            for (int j = 0; j < 4; j++) {
                int n = wn + j * 8 + g;
                unsigned bf[2] = { bV[colb * 64 + (n ^ (8 * cq))],
                                   bV[(colb + 4) * 64 + (n ^ (8 * cq))] };
                mma_tf32(acc_o[j], af, bf);
            }
        }
    }

    // ---- epilogue ----
    float il0 = 1.0f / l0r, il1 = 1.0f / l1r;
    #pragma unroll
    for (int j = 0; j < 4; j++) {
        int c = wn + j * 8 + 2 * cq;
        float* d0 = ctx + ((size_t)(b * NT + t0 + r0)) * ND + h * HD + c;
        float* d1 = ctx + ((size_t)(b * NT + t0 + r1)) * ND + h * HD + c;
        d0[0] = roundtf(acc_o[j][0] * il0); d0[1] = roundtf(acc_o[j][1] * il0);
        d1[0] = roundtf(acc_o[j][2] * il1); d1[1] = roundtf(acc_o[j][3] * il1);
    }
}

// ---------------------------------------------------------------------------
extern "C" void kernel_launch(void* const* d_in, const int* in_sizes, int n_in,
                              void* d_out, int out_size) {
    const float* x    = (const float*)d_in[0];
    const float* pos  = (const float*)d_in[1];
    const float* ln_g = (const float*)d_in[2];
    const float* ln_b = (const float*)d_in[3];
    const float* Wq   = (const float*)d_in[4];
    const float* bq   = (const float*)d_in[5];
    const float* Wk   = (const float*)d_in[6];
    const float* bk   = (const float*)d_in[7];
    const float* Wv   = (const float*)d_in[8];
    const float* bv   = (const float*)d_in[9];
    const float* Wp   = (const float*)d_in[10];
    const float* bp   = (const float*)d_in[11];
    const float* cb   = (const float*)d_in[12];
    const float* pb   = (const float*)d_in[13];
    const float* Wo   = (const float*)d_in[14];
    const float* bo   = (const float*)d_in[15];
    float* out = (float*)d_out;

    float *xn, *q, *k, *v, *p, *ctx, *wr, *posr;
    cudaGetSymbolAddress((void**)&xn,   g_xn);
    cudaGetSymbolAddress((void**)&q,    g_q);
    cudaGetSymbolAddress((void**)&k,    g_kk);
    cudaGetSymbolAddress((void**)&v,    g_v);
    cudaGetSymbolAddress((void**)&p,    g_pp);
    cudaGetSymbolAddress((void**)&ctx,  g_ctx);
    cudaGetSymbolAddress((void**)&wr,   g_wr);
    cudaGetSymbolAddress((void**)&posr, g_posr);

    cudaFuncSetAttribute(flash_attn, cudaFuncAttributeMaxDynamicSharedMemorySize,
                         FLASH_SMEM);
    cudaFuncSetAttribute(proj_batched, cudaFuncAttributeMaxDynamicSharedMemorySize,
                         64 * 1024);
    cudaFuncSetAttribute(gemm_out, cudaFuncAttributeMaxDynamicSharedMemorySize,
                         64 * 1024);

    const int WN = ND * ND;   // 262144

    // 0. Pre-round weights + pos_emb
    RoundSet rs;
    rs.src[0] = Wq;  rs.dst[0] = wr + 0 * WN; rs.n4[0] = WN / 4;
    rs.src[1] = Wk;  rs.dst[1] = wr + 1 * WN; rs.n4[1] = WN / 4;
    rs.src[2] = Wv;  rs.dst[2] = wr + 2 * WN; rs.n4[2] = WN / 4;
    rs.src[3] = Wp;  rs.dst[3] = wr + 3 * WN; rs.n4[3] = WN / 4;
    rs.src[4] = Wo;  rs.dst[4] = wr + 4 * WN; rs.n4[4] = WN / 4;
    rs.src[5] = pos; rs.dst[5] = posr;        rs.n4[5] = (NB * NP * ND) / 4;
    round_copy<<<dim3(512, 6), 256>>>(rs);

    // 1. LayerNorm (rounded output)
    ln_kernel<<<NB * NT, 256>>>(x, ln_g, ln_b, xn);

    // 2. Q/K/V/P projections, batched
    ProjSet ps;
    ps.A[0] = xn;   ps.W[0] = wr + 0 * WN; ps.bias[0] = bq; ps.C[0] = q; ps.M[0] = NB * NT;
    ps.A[1] = xn;   ps.W[1] = wr + 1 * WN; ps.bias[1] = bk; ps.C[1] = k; ps.M[1] = NB * NT;
    ps.A[2] = xn;   ps.W[2] = wr + 2 * WN; ps.bias[2] = bv; ps.C[2] = v; ps.M[2] = NB * NT;
    ps.A[3] = posr; ps.W[3] = wr + 3 * WN; ps.bias[3] = bp; ps.C[3] = p; ps.M[3] = NB * NP;
    proj_batched<<<dim3(4, 128, 4), 256, 64 * 1024>>>(ps);

    // 3. Fused attention
    dim3 ga(NT / 64, NB * NH);
    flash_attn<<<ga, 256, FLASH_SMEM>>>(q, k, v, p, cb, pb, ctx);

    // 4. Output projection -> d_out
    gemm_out<<<dim3(4, 64), 256, 64 * 1024>>>(ctx, wr + 4 * WN, bo, out, NB * NT);
}

// round 17
// speedup vs baseline: 4.6383x; 1.0669x over previous
#include <cuda_runtime.h>

// ---------------------------------------------------------------------------
// Transformer-XL relative multi-head attention, TF32 tensor cores, fused
// flash attention, cp.async prefetch, ldmatrix fragment loads, banded
// position GEMM with per-pair column windows and pair-scoped barriers.
// B=16, T=512, D=512, H=8, hd=64, P=2T-1=1023.
// ---------------------------------------------------------------------------

#define NB 16
#define NT 512
#define ND 512
#define NH 8
#define HD 64
#define NP (2*NT - 1)   // 1023

__device__ float g_xn  [NB*NT*ND];
__device__ float g_q   [NB*NT*ND];
__device__ float g_kk  [NB*NT*ND];
__device__ float g_v   [NB*NT*ND];
__device__ float g_pp  [NB*NP*ND];
__device__ float g_ctx [NB*NT*ND];
__device__ float g_wr  [5 * ND * ND];       // rounded Wq,Wk,Wv,Wp,Wo
__device__ float g_posr[NB*NP*ND];          // rounded pos_emb

// ---------------------------------------------------------------------------
__device__ __forceinline__ unsigned f2tf32(float x) {
    unsigned u;
    asm("cvt.rna.tf32.f32 %0, %1;" : "=r"(u) : "f"(x));
    return u;
}
__device__ __forceinline__ float roundtf(float x) { return __uint_as_float(f2tf32(x)); }

__device__ __forceinline__ void mma_tf32(float* d, const unsigned* a, const unsigned* b) {
    asm volatile(
        "mma.sync.aligned.m16n8k8.row.col.f32.tf32.tf32.f32 "
        "{%0,%1,%2,%3}, {%4,%5,%6,%7}, {%8,%9}, {%0,%1,%2,%3};"
        : "+f"(d[0]), "+f"(d[1]), "+f"(d[2]), "+f"(d[3])
        : "r"(a[0]), "r"(a[1]), "r"(a[2]), "r"(a[3]), "r"(b[0]), "r"(b[1]));
}

__device__ __forceinline__ void ldsm4(unsigned* d, unsigned addr) {
    asm volatile("ldmatrix.sync.aligned.m8n8.x4.shared.b16 {%0,%1,%2,%3}, [%4];"
                 : "=r"(d[0]), "=r"(d[1]), "=r"(d[2]), "=r"(d[3]) : "r"(addr));
}

__device__ __forceinline__ unsigned smaddr(const void* p) {
    return (unsigned)__cvta_generic_to_shared(p);
}
#define CP16(dst, src, pred) \
    asm volatile("cp.async.cg.shared.global [%0], [%1], 16, %2;" \
                 :: "r"(dst), "l"(src), "r"((pred) ? 16 : 0))
#define CP_COMMIT() asm volatile("cp.async.commit_group;")
#define CP_WAIT2()  asm volatile("cp.async.wait_group 2;")
#define CP_WAIT0()  asm volatile("cp.async.wait_group 0;")
#define BAR_PAIR(id) asm volatile("bar.sync %0, 64;" :: "r"(id) : "memory")

// ---------------------------------------------------------------------------
// Prep: round weights + pos_emb to tf32-representable f32
// ---------------------------------------------------------------------------
struct RoundSet { const float* src[6]; float* dst[6]; int n4[6]; };

__global__ void round_copy(RoundSet rs) {
    int z = blockIdx.y;
    int n4 = rs.n4[z];
    const float4* s = (const float4*)rs.src[z];
    float4* d = (float4*)rs.dst[z];
    for (int i = blockIdx.x * blockDim.x + threadIdx.x; i < n4;
         i += gridDim.x * blockDim.x) {
        float4 v = s[i];
        d[i] = make_float4(roundtf(v.x), roundtf(v.y), roundtf(v.z), roundtf(v.w));
    }
}

// ---------------------------------------------------------------------------
// LayerNorm (writes tf32-rounded output)
// ---------------------------------------------------------------------------
__global__ void ln_kernel(const float* __restrict__ x,
                          const float* __restrict__ gam,
                          const float* __restrict__ bet,
                          float* __restrict__ xn) {
    int row = blockIdx.x;
    int tid = threadIdx.x;
    const float* xr = x + (size_t)row * ND;
    float v0 = xr[tid], v1 = xr[tid + 256];
    float s = v0 + v1, ss = v0*v0 + v1*v1;
    #pragma unroll
    for (int o = 16; o > 0; o >>= 1) {
        s  += __shfl_down_sync(0xffffffffu, s,  o);
        ss += __shfl_down_sync(0xffffffffu, ss, o);
    }
    __shared__ float sh[16];
    __shared__ float smu, srs;
    int wid = tid >> 5, lane = tid & 31;
    if (lane == 0) { sh[wid] = s; sh[wid + 8] = ss; }
    __syncthreads();
    if (tid == 0) {
        float t1 = 0.f, t2 = 0.f;
        #pragma unroll
        for (int i = 0; i < 8; i++) { t1 += sh[i]; t2 += sh[i + 8]; }
        float mu  = t1 * (1.0f / ND);
        float var = t2 * (1.0f / ND) - mu * mu;
        smu = mu;
        srs = rsqrtf(var + 1e-5f);
    }
    __syncthreads();
    float mu = smu, rs = srs;
    float* xo = xn + (size_t)row * ND;
    xo[tid]       = roundtf((v0 - mu) * rs * gam[tid]       + bet[tid]);
    xo[tid + 256] = roundtf((v1 - mu) * rs * gam[tid + 256] + bet[tid + 256]);
}

// ---------------------------------------------------------------------------
// TF32 GEMM core: C[M,512] = A[M,512] @ W[512,512]^T + bias.
// 128x128 tile, BK=16, 4-stage cp.async, ldmatrix fragment loads.
// ---------------------------------------------------------------------------
template<bool ROUND>
__device__ __forceinline__ void gemm_core(const float* __restrict__ A,
                                          const float* __restrict__ W,
                                          const float* __restrict__ bias,
                                          float* __restrict__ C, int M,
                                          int m0, int n0,
                                          unsigned* sA, unsigned* sB) {
    const int tid = threadIdx.x, lane = tid & 31, wid = tid >> 5;
    const int g = lane >> 2, cq = lane & 3;
    const int wm = (wid >> 2) * 64, wn = (wid & 3) * 32;

    // ldmatrix geometry
    const int lane7 = lane & 7;
    const int mhi   = lane >> 3;
    const int swg4  = 4 * ((lane7 >> 1) & 3);
    const int rowAg = wm + ((mhi & 1) << 3) + lane7;
    const unsigned coA4 = (unsigned)(((((mhi >> 1) << 2)) ^ swg4) << 2);
    const int rowBg = wn + ((mhi >> 1) << 3) + lane7;
    const unsigned coB4 = (unsigned)(((((mhi & 1) << 2)) ^ swg4) << 2);
    const unsigned aFragB = smaddr(sA) + rowAg * 64;
    const unsigned bFragB = smaddr(sB) + rowBg * 64;

    // copy geometry
    const int r  = tid >> 2;
    const int cc = (tid & 3) * 4;
    const int sc = cc ^ (4 * ((r >> 1) & 3));
    const int e0 = r * 16 + sc, e1 = (r + 64) * 16 + sc;
    const unsigned aB = smaddr(sA), bB = smaddr(sB);

    const int ar0 = m0 + r, ar1 = m0 + r + 64;
    const float* a0 = A + (size_t)(ar0 < M ? ar0 : 0) * 512 + cc;
    const float* a1 = A + (size_t)(ar1 < M ? ar1 : 0) * 512 + cc;
    const float* w0 = W + (size_t)(n0 + r) * 512 + cc;
    const float* w1 = W + (size_t)(n0 + r + 64) * 512 + cc;
    const bool p0 = ar0 < M, p1 = ar1 < M;

    float acc[16][4];
    #pragma unroll
    for (int i = 0; i < 16; i++)
        #pragma unroll
        for (int j = 0; j < 4; j++) acc[i][j] = 0.f;

    auto issue = [&](int stage, int kc) {
        unsigned ab = aB + stage * 8192, bb = bB + stage * 8192;
        int ko = kc * 16;
        CP16(ab + e0 * 4, a0 + ko, p0);
        CP16(ab + e1 * 4, a1 + ko, p1);
        CP16(bb + e0 * 4, w0 + ko, true);
        CP16(bb + e1 * 4, w1 + ko, true);
    };
    auto compute = [&](int stage) {
        const unsigned aSt = aFragB + stage * 8192;
        const unsigned bSt = bFragB + stage * 8192;
        #pragma unroll
        for (int ks = 0; ks < 2; ks++) {
            unsigned kx = ks * 32;
            unsigned af[4][4], b0[4], b1[4];
            #pragma unroll
            for (int i = 0; i < 4; i++)
                ldsm4(af[i], aSt + i * 1024 + (kx ^ coA4));
            ldsm4(b0, bSt + (kx ^ coB4));
            ldsm4(b1, bSt + 1024 + (kx ^ coB4));
            #pragma unroll
            for (int i = 0; i < 4; i++) {
                mma_tf32(acc[i * 4 + 0], af[i], b0);
                mma_tf32(acc[i * 4 + 1], af[i], b0 + 2);
                mma_tf32(acc[i * 4 + 2], af[i], b1);
                mma_tf32(acc[i * 4 + 3], af[i], b1 + 2);
            }
        }
    };

    issue(0, 0); CP_COMMIT();
    issue(1, 1); CP_COMMIT();
    issue(2, 2); CP_COMMIT();
    for (int kc = 0; kc < 32; kc++) {
        CP_WAIT2();
        __syncthreads();
        if (kc + 3 < 32) issue((kc + 3) & 3, kc + 3);
        CP_COMMIT();
        compute(kc & 3);
    }

    #pragma unroll
    for (int i = 0; i < 4; i++) {
        int row = m0 + wm + i * 16 + g;
        #pragma unroll
        for (int j = 0; j < 4; j++) {
            int col = n0 + wn + j * 8 + 2 * cq;
            float b0 = __ldg(&bias[col]), b1 = __ldg(&bias[col + 1]);
            float* v = acc[i * 4 + j];
            if (row < M) {
                float o0 = v[0] + b0, o1 = v[1] + b1;
                C[(size_t)row * 512 + col]     = ROUND ? roundtf(o0) : o0;
                C[(size_t)row * 512 + col + 1] = ROUND ? roundtf(o1) : o1;
            }
            if (row + 8 < M) {
                float o0 = v[2] + b0, o1 = v[3] + b1;
                C[(size_t)(row + 8) * 512 + col]     = ROUND ? roundtf(o0) : o0;
                C[(size_t)(row + 8) * 512 + col + 1] = ROUND ? roundtf(o1) : o1;
            }
        }
    }
}

struct ProjSet {
    const float* A[4]; const float* W[4]; const float* bias[4];
    float* C[4]; int M[4];
};

__global__ __launch_bounds__(256, 2) void proj_batched(ProjSet ps) {
    extern __shared__ unsigned gsm[];
    int z = blockIdx.z;
    int M = ps.M[z];
    int m0 = blockIdx.y * 128;
    if (m0 >= M) return;
    gemm_core<true>(ps.A[z], ps.W[z], ps.bias[z], ps.C[z], M,
                    m0, blockIdx.x * 128, gsm, gsm + 4 * 2048);
}

__global__ __launch_bounds__(256, 2) void gemm_out(const float* __restrict__ A,
                                                   const float* __restrict__ W,
                                                   const float* __restrict__ bias,
                                                   float* __restrict__ C, int M) {
    extern __shared__ unsigned gsm[];
    gemm_core<false>(A, W, bias, C, M, blockIdx.y * 128, blockIdx.x * 128,
                     gsm, gsm + 4 * 2048);
}

// ---------------------------------------------------------------------------
// Fused flash attention.
// rel_shift: band rows [448+j0-t0 .. +126], gather index 63 + j - t.
// Band MMA restricted per warp-pair to the 96-col window [w0, w0+96),
// w0 = min(32, 48-wm), which covers all gathered diagonals [48-wm, 126-wm].
// Pair-scoped bar.sync for fPS/fRed/uP phases (rows are pair-private);
// only the cp.async buffer-rotation barrier is block-wide.
// ---------------------------------------------------------------------------
#define PS_STRIDE 136
#define FLASH_SMEM ((4096*3 + 8192*2 + 16384) * 4 + 64*PS_STRIDE*4 + 128*4)

__global__ __launch_bounds__(256) void flash_attn(
    const float* __restrict__ Q, const float* __restrict__ K,
    const float* __restrict__ V, const float* __restrict__ P,
    const float* __restrict__ cb, const float* __restrict__ pb,
    float* __restrict__ ctx) {
    extern __shared__ char smraw[];
    unsigned* uQc = (unsigned*)smraw;     // 64x64
    unsigned* uQp = uQc + 4096;           // 64x64
    unsigned* uK  = uQp + 4096;           // 2 x 64x64
    unsigned* uV  = uK  + 8192;           // 2 x 64x64
    unsigned* uP  = uV  + 8192;           // 64x64
    unsigned* uB  = uP  + 4096;           // 2 x 128x64
    float* fPS  = (float*)(uB + 16384);   // 64 x PS_STRIDE
    float* fRed = fPS + 64 * PS_STRIDE;   // [2][64]

    const int tid = threadIdx.x, lane = tid & 31, wid = tid >> 5;
    const int g = lane >> 2, cq = lane & 3;
    const int wm = (wid >> 1) * 16, wn = (wid & 1) * 32;
    const int t0 = blockIdx.x * 64;
    const int z = blockIdx.y, b = z >> 3, h = z & 7;
    const int sz = 4 * g;
    const int barid = 1 + (wid >> 1);     // pair barrier id (1..4)

    // band window for this pair / warp
    const int w0  = (48 - wm) < 32 ? (48 - wm) : 32;
    const int wnb = w0 + (wid & 1) * 48;  // this warp's 48-col band start

    // ldmatrix geometry
    const int lane7 = lane & 7;
    const int mhi   = lane >> 3;
    const int swl4  = 4 * lane7;
    const int rowA  = wm + ((mhi & 1) << 3) + lane7;
    const unsigned coA4 = (unsigned)(((((mhi >> 1) << 2)) ^ swl4) << 2);
    const int rowBl = ((mhi >> 1) << 3) + lane7;
    const unsigned coB4 = (unsigned)(((((mhi & 1) << 2)) ^ swl4) << 2);
    const unsigned baseQc = smaddr(uQc) + rowA * 256;
    const unsigned baseQp = smaddr(uQp) + rowA * 256;
    const unsigned basePm = smaddr(uP)  + rowA * 256;
    const unsigned rowKoff = (unsigned)((wn + rowBl) * 256);
    const unsigned rowBoff = (unsigned)((wnb + rowBl) * 256);

    const float* Qb = Q + (size_t)b * NT * ND + h * HD;
    const float* Kb = K + (size_t)b * NT * ND + h * HD;
    const float* Vb = V + (size_t)b * NT * ND + h * HD;
    const float* Pb = P + (size_t)b * NP * ND + h * HD;

    auto issue_tile = [&](int t) {
        int buf = t & 1;
        int jj0 = t * 64;
        int pb0 = 448 + jj0 - t0;
        unsigned kB = smaddr(uK + buf * 4096);
        unsigned vB = smaddr(uV + buf * 4096);
        unsigned bB = smaddr(uB + buf * 8192);
        #pragma unroll
        for (int i = 0; i < 4; i++) {
            int idx = tid + i * 256;
            int r = idx >> 4, c4 = (idx & 15) * 4;
            CP16(kB + (r * 64 + (c4 ^ (4 * (r & 7)))) * 4,
                 Kb + (size_t)(jj0 + r) * ND + c4, true);
            CP16(vB + (r * 64 + (c4 ^ (8 * (r & 3)))) * 4,
                 Vb + (size_t)(jj0 + r) * ND + c4, true);
        }
        #pragma unroll
        for (int i = 0; i < 8; i++) {
            int idx = tid + i * 256;
            int r = idx >> 4, c4 = (idx & 15) * 4;
            CP16(bB + (r * 64 + (c4 ^ (4 * (r & 7)))) * 4,
                 Pb + (size_t)(pb0 + r) * ND + c4, r < 127);
        }
    };

    issue_tile(0);
    CP_COMMIT();

    // ---- Q tile once: qc = q+cb, qp = q+pb ----
    #pragma unroll
    for (int i = 0; i < 4; i++) {
        int idx = tid + i * 256;
        int r = idx >> 4, c4 = (idx & 15) * 4;
        float4 qv  = *reinterpret_cast<const float4*>(Qb + (size_t)(t0 + r) * ND + c4);
        float4 cbv = *reinterpret_cast<const float4*>(cb + h * HD + c4);
        float4 pbv = *reinterpret_cast<const float4*>(pb + h * HD + c4);
        int sc = c4 ^ (4 * (r & 7));
        *reinterpret_cast<uint4*>(&uQc[r * 64 + sc]) =
            make_uint4(f2tf32(qv.x + cbv.x), f2tf32(qv.y + cbv.y),
                       f2tf32(qv.z + cbv.z), f2tf32(qv.w + cbv.w));
        *reinterpret_cast<uint4*>(&uQp[r * 64 + sc]) =
            make_uint4(f2tf32(qv.x + pbv.x), f2tf32(qv.y + pbv.y),
                       f2tf32(qv.z + pbv.z), f2tf32(qv.w + pbv.w));
    }

    float m0r = -1e30f, m1r = -1e30f, l0r = 0.f, l1r = 0.f;

    float acc_o[4][4];
    #pragma unroll
    for (int j = 0; j < 4; j++)
        #pragma unroll
        for (int q4 = 0; q4 < 4; q4++) acc_o[j][q4] = 0.f;

    const int r0 = wm + g, r1 = wm + 8 + g;

    for (int jt = 0; jt < 8; jt++) {
        const int buf = jt & 1;
        const unsigned* bV = uV + buf * 4096;
        const unsigned kFrag = smaddr(uK) + buf * 16384 + rowKoff;
        const unsigned bFrag = smaddr(uB) + buf * 32768 + rowBoff;

        CP_WAIT0();
        __syncthreads();                 // block: tile ready, prev PV done
        if (jt < 7) { issue_tile(jt + 1); CP_COMMIT(); }

        // ---- content MMA: qc @ k^T ----
        float acc_c[4][4];
        #pragma unroll
        for (int j = 0; j < 4; j++)
            #pragma unroll
            for (int q4 = 0; q4 < 4; q4++) acc_c[j][q4] = 0.f;
        #pragma unroll
        for (int ks = 0; ks < 8; ks++) {
            unsigned kx = ks * 32;
            unsigned af[4], b0[4], b1[4];
            ldsm4(af, baseQc + (kx ^ coA4));
            ldsm4(b0, kFrag + (kx ^ coB4));
            ldsm4(b1, kFrag + 4096 + (kx ^ coB4));
            mma_tf32(acc_c[0], af, b0);
            mma_tf32(acc_c[1], af, b0 + 2);
            mma_tf32(acc_c[2], af, b1);
            mma_tf32(acc_c[3], af, b1 + 2);
        }

        // ---- band MMA: qp @ band^T over 48-col warp window -> fPS ----
        {
            float acc_p[6][4];
            #pragma unroll
            for (int j = 0; j < 6; j++)
                #pragma unroll
                for (int q4 = 0; q4 < 4; q4++) acc_p[j][q4] = 0.f;
            #pragma unroll
            for (int ks = 0; ks < 8; ks++) {
                unsigned kx = ks * 32;
                unsigned af[4], b0[4], b1[4], b2[4];
                ldsm4(af, baseQp + (kx ^ coA4));
                ldsm4(b0, bFrag + (kx ^ coB4));
                ldsm4(b1, bFrag + 4096 + (kx ^ coB4));
                ldsm4(b2, bFrag + 8192 + (kx ^ coB4));
                mma_tf32(acc_p[0], af, b0);
                mma_tf32(acc_p[1], af, b0 + 2);
                mma_tf32(acc_p[2], af, b1);
                mma_tf32(acc_p[3], af, b1 + 2);
                mma_tf32(acc_p[4], af, b2);
                mma_tf32(acc_p[5], af, b2 + 2);
            }
            #pragma unroll
            for (int j = 0; j < 6; j++) {
                int c = wnb + j * 8 + 2 * cq;
                *reinterpret_cast<float2*>(&fPS[r0 * PS_STRIDE + c]) =
                    make_float2(acc_p[j][0], acc_p[j][1]);
                *reinterpret_cast<float2*>(&fPS[r1 * PS_STRIDE + c]) =
                    make_float2(acc_p[j][2], acc_p[j][3]);
            }
        }
        BAR_PAIR(barid);                 // pair: fPS visible

        // ---- gather diagonal, combine, row maxima ----
        float s[4][4];
        float rmax0 = -1e30f, rmax1 = -1e30f;
        #pragma unroll
        for (int j = 0; j < 4; j++) {
            int c = wn + j * 8 + 2 * cq;
            s[j][0] = (acc_c[j][0] + fPS[r0 * PS_STRIDE + (63 + c     - r0)]) * 0.125f;
            s[j][1] = (acc_c[j][1] + fPS[r0 * PS_STRIDE + (63 + c + 1 - r0)]) * 0.125f;
            s[j][2] = (acc_c[j][2] + fPS[r1 * PS_STRIDE + (63 + c     - r1)]) * 0.125f;
            s[j][3] = (acc_c[j][3] + fPS[r1 * PS_STRIDE + (63 + c + 1 - r1)]) * 0.125f;
            rmax0 = fmaxf(rmax0, fmaxf(s[j][0], s[j][1]));
            rmax1 = fmaxf(rmax1, fmaxf(s[j][2], s[j][3]));
        }
        rmax0 = fmaxf(rmax0, __shfl_xor_sync(0xffffffffu, rmax0, 1));
        rmax0 = fmaxf(rmax0, __shfl_xor_sync(0xffffffffu, rmax0, 2));
        rmax1 = fmaxf(rmax1, __shfl_xor_sync(0xffffffffu, rmax1, 1));
        rmax1 = fmaxf(rmax1, __shfl_xor_sync(0xffffffffu, rmax1, 2));
        if (cq == 0) {
            fRed[(wid & 1) * 64 + r0] = rmax0;
            fRed[(wid & 1) * 64 + r1] = rmax1;
        }
        BAR_PAIR(barid);                 // pair: maxima visible

        float mn0 = fmaxf(m0r, fmaxf(fRed[r0], fRed[64 + r0]));
        float mn1 = fmaxf(m1r, fmaxf(fRed[r1], fRed[64 + r1]));
        float al0 = __expf(m0r - mn0), al1 = __expf(m1r - mn1);
        m0r = mn0; m1r = mn1;

        // ---- exp, store P (tf32), rescale O, row sums ----
        float rsum0 = 0.f, rsum1 = 0.f;
        #pragma unroll
        for (int j = 0; j < 4; j++) {
            float p00 = __expf(s[j][0] - mn0), p01 = __expf(s[j][1] - mn0);
            float p10 = __expf(s[j][2] - mn1), p11 = __expf(s[j][3] - mn1);
            rsum0 += p00 + p01;
            rsum1 += p10 + p11;
            int c = wn + j * 8 + 2 * cq;
            *reinterpret_cast<uint2*>(&uP[r0 * 64 + (c ^ sz)]) =
                make_uint2(f2tf32(p00), f2tf32(p01));
            *reinterpret_cast<uint2*>(&uP[r1 * 64 + (c ^ sz)]) =
                make_uint2(f2tf32(p10), f2tf32(p11));
            acc_o[j][0] *= al0; acc_o[j][1] *= al0;
            acc_o[j][2] *= al1; acc_o[j][3] *= al1;
        }
        rsum0 += __shfl_xor_sync(0xffffffffu, rsum0, 1);
        rsum0 += __shfl_xor_sync(0xffffffffu, rsum0, 2);
        rsum1 += __shfl_xor_sync(0xffffffffu, rsum1, 1);
        rsum1 += __shfl_xor_sync(0xffffffffu, rsum1, 2);
        if (cq == 0) {
            fRed[(wid & 1) * 64 + r0] = rsum0;
            fRed[(wid & 1) * 64 + r1] = rsum1;
        }
        BAR_PAIR(barid);                 // pair: sums + uP visible

        l0r = l0r * al0 + fRed[r0] + fRed[64 + r0];
        l1r = l1r * al1 + fRed[r1] + fRed[64 + r1];

        // ---- O += P @ V ----  (A via ldmatrix, V scalar: layout mismatch)
        #pragma unroll
        for (int ks = 0; ks < 8; ks++) {
            unsigned kx = ks * 32;
            int colb = ks * 8 + cq;
            unsigned af[4];
            ldsm4(af, basePm + (kx ^ coA4));
            #pragma unroll
            for (int j = 0; j < 4; j++) {
                int n = wn + j * 8 + g;
                unsigned bf[2] = { bV[colb * 64 + (n ^ (8 * cq))],
                                   bV[(colb + 4) * 64 + (n ^ (8 * cq))] };
                mma_tf32(acc_o[j], af, bf);
            }
        }
    }

    // ---- epilogue ----
    float il0 = 1.0f / l0r, il1 = 1.0f / l1r;
    #pragma unroll
    for (int j = 0; j < 4; j++) {
        int c = wn + j * 8 + 2 * cq;
        float* d0 = ctx + ((size_t)(b * NT + t0 + r0)) * ND + h * HD + c;
        float* d1 = ctx + ((size_t)(b * NT + t0 + r1)) * ND + h * HD + c;
        d0[0] = roundtf(acc_o[j][0] * il0); d0[1] = roundtf(acc_o[j][1] * il0);
        d1[0] = roundtf(acc_o[j][2] * il1); d1[1] = roundtf(acc_o[j][3] * il1);
    }
}

// ---------------------------------------------------------------------------
extern "C" void kernel_launch(void* const* d_in, const int* in_sizes, int n_in,
                              void* d_out, int out_size) {
    const float* x    = (const float*)d_in[0];
    const float* pos  = (const float*)d_in[1];
    const float* ln_g = (const float*)d_in[2];
    const float* ln_b = (const float*)d_in[3];
    const float* Wq   = (const float*)d_in[4];
    const float* bq   = (const float*)d_in[5];
    const float* Wk   = (const float*)d_in[6];
    const float* bk   = (const float*)d_in[7];
    const float* Wv   = (const float*)d_in[8];
    const float* bv   = (const float*)d_in[9];
    const float* Wp   = (const float*)d_in[10];
    const float* bp   = (const float*)d_in[11];
    const float* cb   = (const float*)d_in[12];
    const float* pb   = (const float*)d_in[13];
    const float* Wo   = (const float*)d_in[14];
    const float* bo   = (const float*)d_in[15];
    float* out = (float*)d_out;

    float *xn, *q, *k, *v, *p, *ctx, *wr, *posr;
    cudaGetSymbolAddress((void**)&xn,   g_xn);
    cudaGetSymbolAddress((void**)&q,    g_q);
    cudaGetSymbolAddress((void**)&k,    g_kk);
    cudaGetSymbolAddress((void**)&v,    g_v);
    cudaGetSymbolAddress((void**)&p,    g_pp);
    cudaGetSymbolAddress((void**)&ctx,  g_ctx);
    cudaGetSymbolAddress((void**)&wr,   g_wr);
    cudaGetSymbolAddress((void**)&posr, g_posr);

    cudaFuncSetAttribute(flash_attn, cudaFuncAttributeMaxDynamicSharedMemorySize,
                         FLASH_SMEM);
    cudaFuncSetAttribute(proj_batched, cudaFuncAttributeMaxDynamicSharedMemorySize,
                         64 * 1024);
    cudaFuncSetAttribute(gemm_out, cudaFuncAttributeMaxDynamicSharedMemorySize,
                         64 * 1024);

    const int WN = ND * ND;   // 262144

    // 0. Pre-round weights + pos_emb
    RoundSet rs;
    rs.src[0] = Wq;  rs.dst[0] = wr + 0 * WN; rs.n4[0] = WN / 4;
    rs.src[1] = Wk;  rs.dst[1] = wr + 1 * WN; rs.n4[1] = WN / 4;
    rs.src[2] = Wv;  rs.dst[2] = wr + 2 * WN; rs.n4[2] = WN / 4;
    rs.src[3] = Wp;  rs.dst[3] = wr + 3 * WN; rs.n4[3] = WN / 4;
    rs.src[4] = Wo;  rs.dst[4] = wr + 4 * WN; rs.n4[4] = WN / 4;
    rs.src[5] = pos; rs.dst[5] = posr;        rs.n4[5] = (NB * NP * ND) / 4;
    round_copy<<<dim3(512, 6), 256>>>(rs);

    // 1. LayerNorm (rounded output)
    ln_kernel<<<NB * NT, 256>>>(x, ln_g, ln_b, xn);

    // 2. Q/K/V/P projections, batched
    ProjSet ps;
    ps.A[0] = xn;   ps.W[0] = wr + 0 * WN; ps.bias[0] = bq; ps.C[0] = q; ps.M[0] = NB * NT;
    ps.A[1] = xn;   ps.W[1] = wr + 1 * WN; ps.bias[1] = bk; ps.C[1] = k; ps.M[1] = NB * NT;
    ps.A[2] = xn;   ps.W[2] = wr + 2 * WN; ps.bias[2] = bv; ps.C[2] = v; ps.M[2] = NB * NT;
    ps.A[3] = posr; ps.W[3] = wr + 3 * WN; ps.bias[3] = bp; ps.C[3] = p; ps.M[3] = NB * NP;
    proj_batched<<<dim3(4, 128, 4), 256, 64 * 1024>>>(ps);

    // 3. Fused attention
    dim3 ga(NT / 64, NB * NH);
    flash_attn<<<ga, 256, FLASH_SMEM>>>(q, k, v, p, cb, pb, ctx);

    // 4. Output projection -> d_out
    gemm_out<<<dim3(4, 64), 256, 64 * 1024>>>(ctx, wr + 4 * WN, bo, out, NB * NT);
}